// round 11
// baseline (speedup 1.0000x reference)
#include <cuda_runtime.h>
#include <cuda_bf16.h>
#include <mma.h>
#include <math.h>
#include <stdint.h>

using namespace nvcuda;

#define NB   2
#define NN   256
#define NF   64
#define NKF  50
#define NC   256
#define DCAT 179   // 2F + KF + 1

// scratch (static device memory; allocation-free)
__device__ __nv_bfloat16 g_Uhi[(size_t)NB*NN*NN*NC];  // [row=bi*256+j][c'] hi
__device__ __nv_bfloat16 g_Ulo[(size_t)NB*NN*NN*NC];  // lo
__device__ __nv_bfloat16 g_Bhi[NC*NC];                // permuted W_xmix hi [k][n]
__device__ __nv_bfloat16 g_Blo[NC*NC];                // lo
__device__ float g_part[(size_t)1024*768];            // per (m-tile): 256 cols x 3
__device__ float g_hes[NB*NN*NC];                     // [bi][c] c=f*4+hd

__device__ __forceinline__ float siluf(float v){ return v / (1.f + __expf(-v)); }
__device__ __forceinline__ float tanhap(float x){
    float y; asm("tanh.approx.f32 %0, %1;" : "=f"(y) : "f"(x)); return y;
}
__device__ __forceinline__ void bf16split(float x, __nv_bfloat16& hi, __nv_bfloat16& lo){
    hi = __float2bfloat16(x);
    lo = __float2bfloat16(x - __bfloat162float(hi));
}

// ---------------------------------------------------------------------------
// Prep: split + row-permute W_xmix into bf16 hi/lo. B[k][n]: k = c' (hd-major),
// original W_xmix row = (k&63)*4 + (k>>6).
// ---------------------------------------------------------------------------
__global__ void k_prep(const float* __restrict__ W_xmix) {
    const int kk = blockIdx.x, c = threadIdx.x;
    const int grow = ((kk & 63) << 2) + (kk >> 6);
    __nv_bfloat16 hi, lo;
    bf16split(W_xmix[grow*NC + c], hi, lo);
    g_Bhi[kk*NC + c] = hi;
    g_Blo[kk*NC + c] = lo;
}

// ---------------------------------------------------------------------------
// Kernel A: edge MLP + semantic attention softmax (R9 version, unchanged).
// ---------------------------------------------------------------------------
__global__ __launch_bounds__(256, 1) void k_edge(
    const float* __restrict__ h,     const float* __restrict__ x,
    const float* __restrict__ W_in,  const float* __restrict__ b_in,
    const float* __restrict__ means, const float* __restrict__ betas,
    const float* __restrict__ W_o1,  const float* __restrict__ b_o1,
    const float* __restrict__ W_o2,  const float* __restrict__ b_o2,
    const float* __restrict__ W_sem, const float* __restrict__ b_sem)
{
    extern __shared__ __align__(32) float sm[];
    float* sh_h  = sm;                 // 256*65
    float* sWin  = sh_h + NN*65;       // 6400
    float* sWo1  = sWin + 128*NKF;     // 11456
    float* sWo2  = sWo1 + DCAT*64;     // 4096
    float* sWsem = sWo2 + 64*64;       // 256
    float* sbin  = sWsem + 256;
    float* smean = sbin + NKF;
    float* sbeta = smean + NKF;
    float* sbo1  = sbeta + NKF;
    float* sbo2  = sbo1 + 64;
    float* sbsem = sbo2 + 64;
    float* sx    = sbsem + 8;
    float* sLog  = sx + NN*3;
    float* sRed  = sLog + 4*NN;
    float* sHeMat = sWin;              // alias after sync
    float* sAttS  = sWin + 16640;

    const int t  = threadIdx.x;
    const int bi = blockIdx.x;
    const int b  = bi >> 8;
    const int i  = bi & 255;

    for (int l = t; l < NN*NF;   l += 256) sh_h[(l>>6)*65 + (l&63)] = h[b*NN*NF + l];
    for (int l = t; l < 128*NKF; l += 256) sWin[l] = W_in[l];
    for (int l = t; l < DCAT*64; l += 256) sWo1[l] = W_o1[l];
    for (int l = t; l < 64*64;   l += 256) sWo2[l] = W_o2[l];
    sWsem[t] = W_sem[t];
    if (t < NKF) { sbin[t]=b_in[t]; smean[t]=means[t]; sbeta[t]=betas[t]; }
    if (t < 64)  { sbo1[t]=b_o1[t]; sbo2[t]=b_o2[t]; }
    if (t < 4)   sbsem[t]=b_sem[t];
    for (int l = t; l < NN*3; l += 256) sx[l] = x[b*NN*3 + l];
    __syncthreads();

    const int j = t;
    const float dx = sx[j*3+0]-sx[i*3+0];
    const float dy = sx[j*3+1]-sx[i*3+1];
    const float dz = sx[j*3+2]-sx[i*3+2];
    const float ss = dx*dx + dy*dy + dz*dz;
    const float d  = sqrtf(fmaxf(ss, 0.f) + 1e-5f);

    float h1[NKF];
    #pragma unroll
    for (int k = 0; k < NKF; k++) h1[k] = sbin[k];
    const float* hj = sh_h + j*65;
    const float* hi = sh_h + i*65;
    for (int f = 0; f < NF; f++) {
        const float vj = hj[f], vi = hi[f];
        const float2* rj = (const float2*)(sWin + f*NKF);
        const float2* ri = (const float2*)(sWin + (64+f)*NKF);
        #pragma unroll
        for (int k2 = 0; k2 < NKF/2; k2++) {
            float2 wj = rj[k2], wi = ri[k2];
            h1[2*k2]   += vj*wj.x + vi*wi.x;
            h1[2*k2+1] += vj*wj.y + vi*wi.y;
        }
    }

    const float em  = __expf(-d);
    const float cut = (d < 5.f) ? 0.5f*(__cosf(d*0.6283185307179586f)+1.f) : 0.f;
    float rh[NKF];
    #pragma unroll
    for (int k = 0; k < NKF; k++) {
        float dm = em - smean[k];
        rh[k] = cut * __expf(-sbeta[k]*dm*dm) * h1[k];
    }

    float tv[64];
    #pragma unroll
    for (int k = 0; k < 64; k++) tv[k] = sbo1[k];
    auto acc_row = [&](float val, const float* row) {
        const float4* r4 = (const float4*)row;
        #pragma unroll
        for (int q = 0; q < 16; q++) {
            float4 w = r4[q];
            tv[4*q+0] += val*w.x; tv[4*q+1] += val*w.y;
            tv[4*q+2] += val*w.z; tv[4*q+3] += val*w.w;
        }
    };
    for (int f = 0; f < 64; f++) acc_row(hj[f], sWo1 + f*64);
    for (int f = 0; f < 64; f++) acc_row(hi[f], sWo1 + (64+f)*64);
    #pragma unroll
    for (int k = 0; k < NKF; k++) acc_row(rh[k], sWo1 + (128+k)*64);
    acc_row(d, sWo1 + 178*64);
    #pragma unroll
    for (int k = 0; k < 64; k++) tv[k] = siluf(tv[k]);

    float he[64];
    #pragma unroll
    for (int k = 0; k < 64; k++) he[k] = sbo2[k];
    #pragma unroll
    for (int c = 0; c < 64; c++) {
        const float val = tv[c];
        const float4* r4 = (const float4*)(sWo2 + c*64);
        #pragma unroll
        for (int q = 0; q < 16; q++) {
            float4 w = r4[q];
            he[4*q+0] += val*w.x; he[4*q+1] += val*w.y;
            he[4*q+2] += val*w.z; he[4*q+3] += val*w.w;
        }
    }

    float l0=sbsem[0], l1=sbsem[1], l2=sbsem[2], l3=sbsem[3];
    #pragma unroll
    for (int f = 0; f < 64; f++) {
        const float v4 = he[f];
        l0 += v4*sWsem[f*4+0]; l1 += v4*sWsem[f*4+1];
        l2 += v4*sWsem[f*4+2]; l3 += v4*sWsem[f*4+3];
    }
    float lg[4] = {l0, l1, l2, l3};
    #pragma unroll
    for (int hd = 0; hd < 4; hd++) {
        float a = lg[hd];
        a = (a > 0.f) ? a : 2.f*(__expf(0.5f*a) - 1.f);
        if (j == i) a -= 1e5f;
        lg[hd] = a;
    }

    __syncthreads();
    #pragma unroll
    for (int f = 0; f < 64; f++) sHeMat[j*65 + f] = he[f];
    #pragma unroll
    for (int hd = 0; hd < 4; hd++) sLog[hd*NN + j] = lg[hd];
    __syncthreads();

    const int wp = t >> 5, lane = t & 31;
    if (wp < 4) {
        float m = -1e30f;
        for (int q = 0; q < 8; q++) m = fmaxf(m, sLog[wp*NN + lane + 32*q]);
        #pragma unroll
        for (int o = 16; o; o >>= 1) m = fmaxf(m, __shfl_xor_sync(~0u, m, o));
        float s = 0.f;
        for (int q = 0; q < 8; q++) s += __expf(sLog[wp*NN + lane + 32*q] - m);
        #pragma unroll
        for (int o = 16; o; o >>= 1) s += __shfl_xor_sync(~0u, s, o);
        if (lane == 0) { sRed[wp*2] = m; sRed[wp*2+1] = s; }
    }
    __syncthreads();

    float att4[4];
    #pragma unroll
    for (int hd = 0; hd < 4; hd++) {
        att4[hd] = __expf(sLog[hd*NN + j] - sRed[hd*2]) / sRed[hd*2+1];
        sAttS[j*4 + hd] = att4[hd];
    }
    {
        __nv_bfloat162* uh = (__nv_bfloat162*)(g_Uhi + ((size_t)bi*NN + j)*NC);
        __nv_bfloat162* ul = (__nv_bfloat162*)(g_Ulo + ((size_t)bi*NN + j)*NC);
        #pragma unroll
        for (int c2 = 0; c2 < 128; c2++) {
            const int i0 = 2*c2;
            const float u0 = att4[(i0+0)>>6] * he[(i0+0)&63];
            const float u1 = att4[(i0+1)>>6] * he[(i0+1)&63];
            __nv_bfloat16 h0, l0b, h1b, l1b;
            bf16split(u0, h0, l0b);
            bf16split(u1, h1b, l1b);
            uh[c2] = __nv_bfloat162(h0, h1b);
            ul[c2] = __nv_bfloat162(l0b, l1b);
        }
    }
    __syncthreads();

    {
        const int f = t >> 2, hd = t & 3;
        float s = 0.f;
        for (int jj = 0; jj < NN; jj++) s += sHeMat[jj*65 + f] * sAttS[jj*4 + hd];
        g_hes[bi*NC + t] = s;
    }
}

// ---------------------------------------------------------------------------
// Kernel B: persistent-B fused GEMM + tanh + j-reduction.
// grid = 296: nblk = blockIdx.x/148 (128-col half), gg = blockIdx.x%148.
// Each block: B panel resident, sweeps m-tiles gg, gg+148, ... (128 rows each).
// ---------------------------------------------------------------------------
#define SB_LD 136            // bf16 stride for B panel
#define SA_LD 72             // bf16 stride for A chunks
#define SD_LD 132            // float stride for D tile
#define OFF_BHI 0
#define OFF_BLO 69632        // 256*136*2
#define OFF_A   139264       // A buffers: 2 x (hi 18432 + lo 18432)
#define OFF_XH  212992       // 128*4 floats
#define OFF_P   215040       // 256*3 floats
#define SMG_TOTAL 218112

__global__ __launch_bounds__(256, 1) void k_gemm_fused(const float* __restrict__ x)
{
    extern __shared__ __align__(16) char smem[];
    __nv_bfloat16* sBh = (__nv_bfloat16*)(smem + OFF_BHI);
    __nv_bfloat16* sBl = (__nv_bfloat16*)(smem + OFF_BLO);
    float* sD  = (float*)(smem + OFF_A);     // aliases A buffers post-mainloop
    float* sXh = (float*)(smem + OFF_XH);
    float* sP  = (float*)(smem + OFF_P);

    const int t  = threadIdx.x;
    const int w  = t >> 5;
    const int wm = w & 3;       // M sub-tile (32 rows)
    const int wn2 = w >> 2;     // N sub-tile (64 cols)
    const int nblk = blockIdx.x / 148;
    const int gg   = blockIdx.x % 148;

    // ---- stage B panel once: 256 K rows x 128 cols, hi/lo ----
    #pragma unroll
    for (int it = 0; it < 16; it++) {
        const int l = t + it*256;
        const int k = l >> 4, c8 = l & 15;
        *(uint4*)(sBh + k*SB_LD + c8*8) = *(const uint4*)(g_Bhi + k*NC + nblk*128 + c8*8);
        *(uint4*)(sBl + k*SB_LD + c8*8) = *(const uint4*)(g_Blo + k*NC + nblk*128 + c8*8);
    }
    __syncthreads();

    for (int m = gg; m < 1024; m += 148) {
        // stage A chunk 0 into buf 0
        {
            __nv_bfloat16* ah = (__nv_bfloat16*)(smem + OFF_A);
            __nv_bfloat16* al = (__nv_bfloat16*)(smem + OFF_A + 18432);
            #pragma unroll
            for (int it = 0; it < 4; it++) {
                const int l = t + it*256;
                const int row = l >> 3, g8 = l & 7;
                *(uint4*)(ah + row*SA_LD + g8*8) = *(const uint4*)(g_Uhi + ((size_t)m*128 + row)*NC + g8*8);
                *(uint4*)(al + row*SA_LD + g8*8) = *(const uint4*)(g_Ulo + ((size_t)m*128 + row)*NC + g8*8);
            }
        }
        __syncthreads();

        wmma::fragment<wmma::accumulator,16,16,16,float> acc[2][4];
        #pragma unroll
        for (int mi = 0; mi < 2; mi++)
            #pragma unroll
            for (int ni = 0; ni < 4; ni++) wmma::fill_fragment(acc[mi][ni], 0.f);

        for (int kc = 0; kc < 4; kc++) {
            const int buf = kc & 1;
            __nv_bfloat16* cah = (__nv_bfloat16*)(smem + OFF_A + buf*36864);
            __nv_bfloat16* cal = (__nv_bfloat16*)(smem + OFF_A + buf*36864 + 18432);

            // prefetch next chunk into registers (overlaps with MMA below)
            uint4 ph[4], pl[4];
            int prow[4], pg8[4];
            if (kc < 3) {
                #pragma unroll
                for (int it = 0; it < 4; it++) {
                    const int l = t + it*256;
                    prow[it] = l >> 3; pg8[it] = l & 7;
                    ph[it] = *(const uint4*)(g_Uhi + ((size_t)m*128 + prow[it])*NC + (kc+1)*64 + pg8[it]*8);
                    pl[it] = *(const uint4*)(g_Ulo + ((size_t)m*128 + prow[it])*NC + (kc+1)*64 + pg8[it]*8);
                }
            }

            // mainloop on current buffer
            #pragma unroll
            for (int ks = 0; ks < 4; ks++) {
                wmma::fragment<wmma::matrix_a,16,16,16,__nv_bfloat16,wmma::row_major> ah[2], al[2];
                #pragma unroll
                for (int mi = 0; mi < 2; mi++) {
                    wmma::load_matrix_sync(ah[mi], cah + (wm*32 + mi*16)*SA_LD + ks*16, SA_LD);
                    wmma::load_matrix_sync(al[mi], cal + (wm*32 + mi*16)*SA_LD + ks*16, SA_LD);
                }
                wmma::fragment<wmma::matrix_b,16,16,16,__nv_bfloat16,wmma::row_major> bh[4], bl[4];
                #pragma unroll
                for (int ni = 0; ni < 4; ni++) {
                    wmma::load_matrix_sync(bh[ni], sBh + (kc*64 + ks*16)*SB_LD + wn2*64 + ni*16, SB_LD);
                    wmma::load_matrix_sync(bl[ni], sBl + (kc*64 + ks*16)*SB_LD + wn2*64 + ni*16, SB_LD);
                }
                // term-major order: spread same-acc dependencies 8 apart
                #pragma unroll
                for (int ni = 0; ni < 4; ni++)
                    #pragma unroll
                    for (int mi = 0; mi < 2; mi++)
                        wmma::mma_sync(acc[mi][ni], ah[mi], bh[ni], acc[mi][ni]);
                #pragma unroll
                for (int ni = 0; ni < 4; ni++)
                    #pragma unroll
                    for (int mi = 0; mi < 2; mi++)
                        wmma::mma_sync(acc[mi][ni], ah[mi], bl[ni], acc[mi][ni]);
                #pragma unroll
                for (int ni = 0; ni < 4; ni++)
                    #pragma unroll
                    for (int mi = 0; mi < 2; mi++)
                        wmma::mma_sync(acc[mi][ni], al[mi], bh[ni], acc[mi][ni]);
            }

            if (kc < 3) {
                __nv_bfloat16* nah = (__nv_bfloat16*)(smem + OFF_A + (buf^1)*36864);
                __nv_bfloat16* nal = (__nv_bfloat16*)(smem + OFF_A + (buf^1)*36864 + 18432);
                #pragma unroll
                for (int it = 0; it < 4; it++) {
                    *(uint4*)(nah + prow[it]*SA_LD + pg8[it]*8) = ph[it];
                    *(uint4*)(nal + prow[it]*SA_LD + pg8[it]*8) = pl[it];
                }
            }
            __syncthreads();
        }

        // ---- fused epilogue: D -> tanh -> xhat-weighted j-reduction ----
        #pragma unroll
        for (int mi = 0; mi < 2; mi++)
            #pragma unroll
            for (int ni = 0; ni < 4; ni++)
                wmma::store_matrix_sync(sD + (wm*32 + mi*16)*SD_LD + wn2*64 + ni*16,
                                        acc[mi][ni], SD_LD, wmma::mem_row_major);
        if (t < 128) {
            const int grow = m*128 + t;
            const int bi = grow >> 8, j = grow & 255;
            const int b = bi >> 8, i = bi & 255;
            const float dx = x[(b*NN+j)*3+0] - x[(b*NN+i)*3+0];
            const float dy = x[(b*NN+j)*3+1] - x[(b*NN+i)*3+1];
            const float dz = x[(b*NN+j)*3+2] - x[(b*NN+i)*3+2];
            const float ssq = dx*dx + dy*dy + dz*dz;
            const float dd  = sqrtf(fmaxf(ssq, 0.f) + 1e-5f);
            const float inv = 1.f/(dd + 1e-5f);
            sXh[t*4+0] = dx*inv; sXh[t*4+1] = dy*inv; sXh[t*4+2] = dz*inv;
        }
        __syncthreads();
        {
            const int c = t & 127, hh = t >> 7;
            float s0 = 0.f, s1 = 0.f, s2 = 0.f;
            #pragma unroll 4
            for (int r = hh*64; r < hh*64 + 64; r++) {
                const float tv = tanhap(sD[r*SD_LD + c]);
                s0 += tv * sXh[r*4+0];
                s1 += tv * sXh[r*4+1];
                s2 += tv * sXh[r*4+2];
            }
            sP[t*3+0] = s0; sP[t*3+1] = s1; sP[t*3+2] = s2;
        }
        __syncthreads();
        if (t < 128) {
            #pragma unroll
            for (int dd = 0; dd < 3; dd++)
                g_part[(size_t)m*768 + (nblk*128 + t)*3 + dd] =
                    sP[t*3+dd] + sP[(128+t)*3+dd];
        }
        __syncthreads();   // protect sD/sXh/sP before next m-tile staging
    }
}

// ---------------------------------------------------------------------------
// Kernel C: combine tile partials + node tail. One block per (b,i).
// ---------------------------------------------------------------------------
__global__ __launch_bounds__(256, 1) void k_tail(
    const float* __restrict__ h,    const float* __restrict__ x,
    const float* __restrict__ v,
    const float* __restrict__ W_p1, const float* __restrict__ b_p1,
    const float* __restrict__ W_p2, const float* __restrict__ b_p2,
    const float* __restrict__ W_n1, const float* __restrict__ b_n1,
    const float* __restrict__ W_n2, const float* __restrict__ b_n2,
    const float* __restrict__ W_v1, const float* __restrict__ b_v1,
    const float* __restrict__ W_v2, const float* __restrict__ W_vmix,
    float* __restrict__ out)
{
    __shared__ float sComb[768], sHes[256], sCn[256];
    __shared__ float sHi[64], sT1[64], sT2[64], sHn[64], sMisc[16];

    const int t  = threadIdx.x;
    const int bi = blockIdx.x;
    const int b  = bi >> 8;
    const int i  = bi & 255;
    const int w  = t >> 5, lane = t & 31;

    sHes[t] = g_hes[bi*NC + t];
    if (t < 64) sHi[t] = h[(b*NN + i)*64 + t];
    {
        const size_t p0 = (size_t)(bi*2)*768, p1 = (size_t)(bi*2+1)*768;
        #pragma unroll
        for (int dd = 0; dd < 3; dd++)
            sComb[t*3+dd] = (g_part[p0 + t*3+dd] + g_part[p1 + t*3+dd]) * (1.f/NN);
    }
    __syncthreads();

    {
        const float c0 = sComb[t*3+0], c1 = sComb[t*3+1], c2 = sComb[t*3+2];
        sCn[t] = c0*c0 + c1*c1 + c2*c2;
    }
    __syncthreads();
    if (t < 64) {
        float a = b_p1[t];
        for (int c = 0; c < 256; c++) a += sCn[c]*W_p1[c*64 + t];
        sT1[t] = siluf(a);
    }
    __syncthreads();
    if (t < 64) {
        float a = b_p2[t];
        for (int c = 0; c < 64; c++) a += sT1[c]*W_p2[c*64 + t];
        sT2[t] = siluf(a);
    }
    __syncthreads();
    if (t < 64) {
        float a = b_n1[t];
        for (int r = 0; r < 64;  r++) a += sHi[r] *W_n1[r*64 + t];
        for (int r = 0; r < 256; r++) a += sHes[r]*W_n1[(64+r)*64 + t];
        for (int r = 0; r < 64;  r++) a += sT2[r] *W_n1[(320+r)*64 + t];
        sT1[t] = siluf(a);
    }
    __syncthreads();
    if (t < 64) {
        float a = b_n2[t];
        for (int c = 0; c < 64; c++) a += sT1[c]*W_n2[c*64 + t];
        const float hn = sHi[t] + siluf(a);
        sHn[t] = hn;
        out[(b*NN + i)*64 + t] = hn;
    }
    __syncthreads();
    if (t < 64) {
        float a = b_v1[t];
        for (int c = 0; c < 64; c++) a += sHn[c]*W_v1[c*64 + t];
        sT1[t] = siluf(a);
    }
    __syncthreads();
    if (w == 0) {
        float s = sT1[lane]*W_v2[lane] + sT1[lane+32]*W_v2[lane+32];
        #pragma unroll
        for (int o = 16; o; o >>= 1) s += __shfl_xor_sync(~0u, s, o);
        if (lane == 0) sMisc[0] = 2.f/(1.f + __expf(-s));
    }
    if (w >= 1 && w <= 3) {
        const int dd = w - 1;
        float s = 0.f;
        for (int q2 = 0; q2 < 8; q2++)
            s += sComb[(lane + 32*q2)*3 + dd]*W_vmix[lane + 32*q2];
        #pragma unroll
        for (int o = 16; o; o >>= 1) s += __shfl_xor_sync(~0u, s, o);
        if (lane == 0) sMisc[1+dd] = s;
    }
    __syncthreads();
    if (t < 3) {
        const float vn = sMisc[1+t] + sMisc[0]*v[(b*NN+i)*3 + t];
        const float xn = x[(b*NN+i)*3 + t] + vn;
        out[NB*NN*64 + (b*NN+i)*3 + t]           = xn;
        out[NB*NN*64 + NB*NN*3 + (b*NN+i)*3 + t] = vn;
    }
}

// ---------------------------------------------------------------------------
extern "C" void kernel_launch(void* const* d_in, const int* in_sizes, int n_in,
                              void* d_out, int out_size)
{
    const float* h      = (const float*)d_in[0];
    const float* x      = (const float*)d_in[1];
    const float* v      = (const float*)d_in[2];
    const float* W_in   = (const float*)d_in[3];
    const float* b_in   = (const float*)d_in[4];
    const float* means  = (const float*)d_in[5];
    const float* betas  = (const float*)d_in[6];
    const float* W_o1   = (const float*)d_in[7];
    const float* b_o1   = (const float*)d_in[8];
    const float* W_o2   = (const float*)d_in[9];
    const float* b_o2   = (const float*)d_in[10];
    const float* W_sem  = (const float*)d_in[11];
    const float* b_sem  = (const float*)d_in[12];
    const float* W_xmix = (const float*)d_in[13];
    const float* W_p1   = (const float*)d_in[14];
    const float* b_p1   = (const float*)d_in[15];
    const float* W_p2   = (const float*)d_in[16];
    const float* b_p2   = (const float*)d_in[17];
    const float* W_n1   = (const float*)d_in[18];
    const float* b_n1   = (const float*)d_in[19];
    const float* W_n2   = (const float*)d_in[20];
    const float* b_n2   = (const float*)d_in[21];
    const float* W_v1   = (const float*)d_in[22];
    const float* b_v1   = (const float*)d_in[23];
    const float* W_v2   = (const float*)d_in[24];
    const float* W_vmix = (const float*)d_in[25];
    float* out = (float*)d_out;

    const size_t smA = (size_t)(NN*65 + 128*NKF + DCAT*64 + 64*64 + 256
                                + 3*NKF + 2*64 + 8 + NN*3 + 4*NN + 16) * sizeof(float);

    cudaFuncSetAttribute(k_edge,       cudaFuncAttributeMaxDynamicSharedMemorySize, (int)smA);
    cudaFuncSetAttribute(k_gemm_fused, cudaFuncAttributeMaxDynamicSharedMemorySize, SMG_TOTAL);

    k_prep<<<NC, NC>>>(W_xmix);
    k_edge<<<NB*NN, 256, smA>>>(h, x, W_in, b_in, means, betas,
                                W_o1, b_o1, W_o2, b_o2, W_sem, b_sem);
    k_gemm_fused<<<296, 256, SMG_TOTAL>>>(x);
    k_tail<<<NB*NN, 256>>>(h, x, v, W_p1, b_p1, W_p2, b_p2,
                           W_n1, b_n1, W_n2, b_n2, W_v1, b_v1,
                           W_v2, W_vmix, out);
}

// round 12
// speedup vs baseline: 1.3099x; 1.3099x over previous
#include <cuda_runtime.h>
#include <cuda_bf16.h>
#include <mma.h>
#include <math.h>
#include <stdint.h>

using namespace nvcuda;

#define NB   2
#define NN   256
#define NF   64
#define NKF  50
#define NC   256
#define DCAT 179   // 2F + KF + 1

// scratch (static device memory; allocation-free)
__device__ __nv_bfloat16 g_Uhi[(size_t)NB*NN*NN*NC];  // [row=bi*256+j][c'] hi
__device__ __nv_bfloat16 g_Ulo[(size_t)NB*NN*NN*NC];  // lo
__device__ __nv_bfloat16 g_Bhi[NC*NC];                // permuted W_xmix hi [k][n]
__device__ __nv_bfloat16 g_Blo[NC*NC];                // lo
__device__ float g_D[(size_t)NB*NN*NN*NC];            // GEMM output (134MB)
__device__ float g_hes[NB*NN*NC];                     // [bi][c] c=f*4+hd
__device__ float g_hw1[NB*NN*NKF];                    // h @ W_in[0:64]
__device__ float g_hw2[NB*NN*NKF];                    // h @ W_in[64:128]
__device__ float g_P1[NB*NN*64];                      // h @ W_o1[0:64]
__device__ float g_P2[NB*NN*64];                      // h @ W_o1[64:128]

__device__ __forceinline__ float siluf(float v){ return v / (1.f + __expf(-v)); }
__device__ __forceinline__ float tanhap(float x){
    float y; asm("tanh.approx.f32 %0, %1;" : "=f"(y) : "f"(x)); return y;
}
__device__ __forceinline__ void bf16split(float x, __nv_bfloat16& hi, __nv_bfloat16& lo){
    hi = __float2bfloat16(x);
    lo = __float2bfloat16(x - __bfloat162float(hi));
}

// ---------------------------------------------------------------------------
// Prep 1: split + row-permute W_xmix into bf16 hi/lo.
// ---------------------------------------------------------------------------
__global__ void k_prep(const float* __restrict__ W_xmix) {
    const int kk = blockIdx.x, c = threadIdx.x;
    const int grow = ((kk & 63) << 2) + (kk >> 6);
    __nv_bfloat16 hi, lo;
    bf16split(W_xmix[grow*NC + c], hi, lo);
    g_Bhi[kk*NC + c] = hi;
    g_Blo[kk*NC + c] = lo;
}

// ---------------------------------------------------------------------------
// Prep 2: per-node precomputes hw1/hw2 (h@W_in halves) and P1/P2 (h@W_o1
// halves). One block per node row, 128 threads.
// ---------------------------------------------------------------------------
__global__ __launch_bounds__(128) void k_pre2(
    const float* __restrict__ h, const float* __restrict__ W_in,
    const float* __restrict__ W_o1)
{
    __shared__ float sh[64];
    const int row = blockIdx.x;   // 0..NB*NN-1
    const int t = threadIdx.x;
    if (t < 64) sh[t] = h[row*64 + t];
    __syncthreads();
    if (t < 64) {
        float p1 = 0.f, p2 = 0.f;
        #pragma unroll 8
        for (int f = 0; f < 64; f++) {
            p1 += sh[f]*W_o1[f*64 + t];
            p2 += sh[f]*W_o1[(64+f)*64 + t];
        }
        g_P1[row*64 + t] = p1;
        g_P2[row*64 + t] = p2;
    } else if (t < 64 + NKF) {
        const int k = t - 64;
        float w1 = 0.f, w2 = 0.f;
        #pragma unroll 8
        for (int f = 0; f < 64; f++) {
            w1 += sh[f]*W_in[f*NKF + k];
            w2 += sh[f]*W_in[(64+f)*NKF + k];
        }
        g_hw1[row*NKF + k] = w1;
        g_hw2[row*NKF + k] = w2;
    }
}

// ---------------------------------------------------------------------------
// Kernel A v2: edge MLP using precomputes. Per-pair work: rbf GEMV + W_o2
// + sem only. One block per (b,i), thread j per pair. 2 blocks/SM target.
// ---------------------------------------------------------------------------
__global__ __launch_bounds__(256, 2) void k_edge(
    const float* __restrict__ x,
    const float* __restrict__ b_in,
    const float* __restrict__ means, const float* __restrict__ betas,
    const float* __restrict__ W_o1,  const float* __restrict__ b_o1,
    const float* __restrict__ W_o2,  const float* __restrict__ b_o2,
    const float* __restrict__ W_sem, const float* __restrict__ b_sem)
{
    extern __shared__ __align__(32) float sm[];
    float* sWo1r = sm;                 // 51*64 = 3264 (rows 128..178)
    float* sWo2  = sWo1r + 51*64;      // 4096
    float* sWsem = sWo2 + 4096;        // 256
    float* sbin  = sWsem + 256;        // 50
    float* smean = sbin + NKF;         // 50
    float* sbeta = smean + NKF;        // 50
    float* sbo1  = sbeta + NKF;        // 64
    float* sbo2  = sbo1 + 64;          // 64
    float* sbsem = sbo2 + 64;          // 8
    float* sP2   = sbsem + 8;          // 64
    float* shw2  = sP2 + 64;           // 64 (50 used)
    float* sx    = shw2 + 64;          // 768
    float* sLog  = sx + NN*3;          // 1024
    float* sRed  = sLog + 4*NN;        // 16
    float* sHeMat= sRed + 16;          // 256*65 = 16640
    float* sAttS = sHeMat + 16640;     // 1024

    const int t  = threadIdx.x;
    const int bi = blockIdx.x;
    const int b  = bi >> 8;
    const int i  = bi & 255;

    for (int l = t; l < 51*64; l += 256) sWo1r[l] = W_o1[128*64 + l];
    for (int l = t; l < 4096;  l += 256) sWo2[l] = W_o2[l];
    sWsem[t] = W_sem[t];
    if (t < NKF) { sbin[t]=b_in[t]; smean[t]=means[t]; sbeta[t]=betas[t]; }
    if (t < 64)  { sbo1[t]=b_o1[t]; sbo2[t]=b_o2[t];
                   sP2[t] = g_P2[(b*NN+i)*64 + t]; }
    if (t < NKF) shw2[t] = g_hw2[(b*NN+i)*NKF + t];
    if (t < 4)   sbsem[t]=b_sem[t];
    for (int l = t; l < NN*3; l += 256) sx[l] = x[b*NN*3 + l];
    __syncthreads();

    const int j = t;
    const float dx = sx[j*3+0]-sx[i*3+0];
    const float dy = sx[j*3+1]-sx[i*3+1];
    const float dz = sx[j*3+2]-sx[i*3+2];
    const float ss = dx*dx + dy*dy + dz*dz;
    const float d  = sqrtf(fmaxf(ss, 0.f) + 1e-5f);
    const float em  = __expf(-d);
    const float cut = (d < 5.f) ? 0.5f*(__cosf(d*0.6283185307179586f)+1.f) : 0.f;

    // --- tv init: P1[j] + P2[i] + b_o1 + d * W_o1[178] ---
    float tv[64];
    {
        const float4* p1r = (const float4*)(g_P1 + (b*NN+j)*64);
        const float4* dr  = (const float4*)(sWo1r + 50*64);
        #pragma unroll
        for (int q = 0; q < 16; q++) {
            float4 p = p1r[q];
            float4 w = dr[q];
            tv[4*q+0] = p.x + sP2[4*q+0] + sbo1[4*q+0] + d*w.x;
            tv[4*q+1] = p.y + sP2[4*q+1] + sbo1[4*q+1] + d*w.y;
            tv[4*q+2] = p.z + sP2[4*q+2] + sbo1[4*q+2] + d*w.z;
            tv[4*q+3] = p.w + sP2[4*q+3] + sbo1[4*q+3] + d*w.w;
        }
    }
    // --- rbf terms, fused (no rh array) ---
    {
        const float* hw1r = g_hw1 + (b*NN+j)*NKF;
        #pragma unroll 2
        for (int k = 0; k < NKF; k++) {
            const float h1 = hw1r[k] + shw2[k] + sbin[k];
            const float dm = em - smean[k];
            const float rh = cut * __expf(-sbeta[k]*dm*dm) * h1;
            const float4* r4 = (const float4*)(sWo1r + k*64);
            #pragma unroll
            for (int q = 0; q < 16; q++) {
                float4 w = r4[q];
                tv[4*q+0] += rh*w.x; tv[4*q+1] += rh*w.y;
                tv[4*q+2] += rh*w.z; tv[4*q+3] += rh*w.w;
            }
        }
    }
    #pragma unroll
    for (int k = 0; k < 64; k++) tv[k] = siluf(tv[k]);

    // --- he = tv @ W_o2 + b_o2 ---
    float he[64];
    #pragma unroll
    for (int k = 0; k < 64; k++) he[k] = sbo2[k];
    #pragma unroll
    for (int c = 0; c < 64; c++) {
        const float val = tv[c];
        const float4* r4 = (const float4*)(sWo2 + c*64);
        #pragma unroll
        for (int q = 0; q < 16; q++) {
            float4 w = r4[q];
            he[4*q+0] += val*w.x; he[4*q+1] += val*w.y;
            he[4*q+2] += val*w.z; he[4*q+3] += val*w.w;
        }
    }

    // --- semantic logits + celu(alpha=2) + self-mask ---
    float l0=sbsem[0], l1=sbsem[1], l2=sbsem[2], l3=sbsem[3];
    #pragma unroll
    for (int f = 0; f < 64; f++) {
        const float v4 = he[f];
        l0 += v4*sWsem[f*4+0]; l1 += v4*sWsem[f*4+1];
        l2 += v4*sWsem[f*4+2]; l3 += v4*sWsem[f*4+3];
    }
    float lg[4] = {l0, l1, l2, l3};
    #pragma unroll
    for (int hd = 0; hd < 4; hd++) {
        float a = lg[hd];
        a = (a > 0.f) ? a : 2.f*(__expf(0.5f*a) - 1.f);
        if (j == i) a -= 1e5f;
        sLog[hd*NN + j] = a;
    }
    #pragma unroll
    for (int f = 0; f < 64; f++) sHeMat[j*65 + f] = he[f];
    __syncthreads();

    // --- softmax over j, one warp per head ---
    const int wp = t >> 5, lane = t & 31;
    if (wp < 4) {
        float m = -1e30f;
        for (int q = 0; q < 8; q++) m = fmaxf(m, sLog[wp*NN + lane + 32*q]);
        #pragma unroll
        for (int o = 16; o; o >>= 1) m = fmaxf(m, __shfl_xor_sync(~0u, m, o));
        float s = 0.f;
        for (int q = 0; q < 8; q++) s += __expf(sLog[wp*NN + lane + 32*q] - m);
        #pragma unroll
        for (int o = 16; o; o >>= 1) s += __shfl_xor_sync(~0u, s, o);
        if (lane == 0) { sRed[wp*2] = m; sRed[wp*2+1] = s; }
    }
    __syncthreads();

    float att4[4];
    #pragma unroll
    for (int hd = 0; hd < 4; hd++) {
        att4[hd] = __expf(sLog[hd*NN + j] - sRed[hd*2]) / sRed[hd*2+1];
        sAttS[j*4 + hd] = att4[hd];
    }
    // write U row (c' = hd*64 + f) as bf16 hi/lo
    {
        __nv_bfloat162* uh = (__nv_bfloat162*)(g_Uhi + ((size_t)bi*NN + j)*NC);
        __nv_bfloat162* ul = (__nv_bfloat162*)(g_Ulo + ((size_t)bi*NN + j)*NC);
        #pragma unroll
        for (int c2 = 0; c2 < 128; c2++) {
            const int i0 = 2*c2;
            const float u0 = att4[(i0+0)>>6] * he[(i0+0)&63];
            const float u1 = att4[(i0+1)>>6] * he[(i0+1)&63];
            __nv_bfloat16 h0, l0b, h1b, l1b;
            bf16split(u0, h0, l0b);
            bf16split(u1, h1b, l1b);
            uh[c2] = __nv_bfloat162(h0, h1b);
            ul[c2] = __nv_bfloat162(l0b, l1b);
        }
    }
    __syncthreads();

    // --- h_e column sums (c = f*4 + hd) ---
    {
        const int f = t >> 2, hd = t & 3;
        float s = 0.f;
        for (int jj = 0; jj < NN; jj++) s += sHeMat[jj*65 + f] * sAttS[jj*4 + hd];
        g_hes[bi*NC + t] = s;
    }
}

// ---------------------------------------------------------------------------
// Kernel B: ONE big GEMM  D[131072,256] = U @ W' (R9 version, at HMMA ceiling).
// ---------------------------------------------------------------------------
#define GLA 72
#define GLB 136

__global__ __launch_bounds__(256, 2) void k_gemm()
{
    extern __shared__ __align__(16) char gsm[];
    __nv_bfloat16* sAhi = (__nv_bfloat16*)gsm;      // 128*72
    __nv_bfloat16* sAlo = sAhi + 128*GLA;
    __nv_bfloat16* sBhi = sAlo + 128*GLA;           // 64*136
    __nv_bfloat16* sBlo = sBhi + 64*GLB;

    const int t    = threadIdx.x;
    const int mblk = blockIdx.x >> 1;
    const int nblk = blockIdx.x & 1;
    const int w    = t >> 5;
    const int wm   = w & 3;
    const int wn2  = w >> 2;

    wmma::fragment<wmma::accumulator,16,16,16,float> acc[2][4];
    #pragma unroll
    for (int mi = 0; mi < 2; mi++)
        #pragma unroll
        for (int ni = 0; ni < 4; ni++) wmma::fill_fragment(acc[mi][ni], 0.f);

    for (int kc = 0; kc < 4; kc++) {
        {
            const size_t gb = ((size_t)mblk*128)*NC + kc*64;
            #pragma unroll
            for (int it = 0; it < 4; it++) {
                const int l = t + it*256;
                const int row = l >> 3, c8 = l & 7;
                *(uint4*)(sAhi + row*GLA + c8*8) = *(const uint4*)(g_Uhi + gb + (size_t)row*NC + c8*8);
                *(uint4*)(sAlo + row*GLA + c8*8) = *(const uint4*)(g_Ulo + gb + (size_t)row*NC + c8*8);
            }
        }
        {
            const int gb = (kc*64)*NC + nblk*128;
            #pragma unroll
            for (int it = 0; it < 4; it++) {
                const int l = t + it*256;
                const int row = l >> 4, c8 = l & 15;
                *(uint4*)(sBhi + row*GLB + c8*8) = *(const uint4*)(g_Bhi + gb + row*NC + c8*8);
                *(uint4*)(sBlo + row*GLB + c8*8) = *(const uint4*)(g_Blo + gb + row*NC + c8*8);
            }
        }
        __syncthreads();

        #pragma unroll
        for (int ks = 0; ks < 4; ks++) {
            wmma::fragment<wmma::matrix_a,16,16,16,__nv_bfloat16,wmma::row_major> ah[2], al[2];
            #pragma unroll
            for (int mi = 0; mi < 2; mi++) {
                wmma::load_matrix_sync(ah[mi], sAhi + (wm*32 + mi*16)*GLA + ks*16, GLA);
                wmma::load_matrix_sync(al[mi], sAlo + (wm*32 + mi*16)*GLA + ks*16, GLA);
            }
            #pragma unroll
            for (int ni = 0; ni < 4; ni++) {
                wmma::fragment<wmma::matrix_b,16,16,16,__nv_bfloat16,wmma::row_major> bh, bl;
                wmma::load_matrix_sync(bh, sBhi + (ks*16)*GLB + wn2*64 + ni*16, GLB);
                wmma::load_matrix_sync(bl, sBlo + (ks*16)*GLB + wn2*64 + ni*16, GLB);
                #pragma unroll
                for (int mi = 0; mi < 2; mi++) {
                    wmma::mma_sync(acc[mi][ni], ah[mi], bh, acc[mi][ni]);
                    wmma::mma_sync(acc[mi][ni], ah[mi], bl, acc[mi][ni]);
                    wmma::mma_sync(acc[mi][ni], al[mi], bh, acc[mi][ni]);
                }
            }
        }
        __syncthreads();
    }

    #pragma unroll
    for (int mi = 0; mi < 2; mi++)
        #pragma unroll
        for (int ni = 0; ni < 4; ni++) {
            float* dst = g_D + ((size_t)mblk*128 + wm*32 + mi*16)*NC
                             + nblk*128 + wn2*64 + ni*16;
            wmma::store_matrix_sync(dst, acc[mi][ni], NC, wmma::mem_row_major);
        }
}

// ---------------------------------------------------------------------------
// Kernel C: tanh + xhat-weighted j-reduction over D + full node tail (R9).
// ---------------------------------------------------------------------------
__global__ __launch_bounds__(256, 1) void k_reduce(
    const float* __restrict__ h,    const float* __restrict__ x,
    const float* __restrict__ v,
    const float* __restrict__ W_p1, const float* __restrict__ b_p1,
    const float* __restrict__ W_p2, const float* __restrict__ b_p2,
    const float* __restrict__ W_n1, const float* __restrict__ b_n1,
    const float* __restrict__ W_n2, const float* __restrict__ b_n2,
    const float* __restrict__ W_v1, const float* __restrict__ b_v1,
    const float* __restrict__ W_v2, const float* __restrict__ W_vmix,
    float* __restrict__ out)
{
    extern __shared__ __align__(16) float rsm[];
    float* sStage = rsm;               // 32*256
    float* sXh    = sStage + 32*256;   // 1024
    float* sComb  = sXh + 1024;        // 768
    float* sHes   = sComb + 768;       // 256
    float* sHi    = sHes + 256;        // 64
    float* sT1    = sHi + 64;          // 64
    float* sT2    = sT1 + 64;          // 64
    float* sHn    = sT2 + 64;          // 64
    float* sMisc  = sHn + 64;          // 16
    float* sCn    = sStage;            // alias after staging done

    const int t  = threadIdx.x;
    const int bi = blockIdx.x;
    const int b  = bi >> 8;
    const int i  = bi & 255;
    const int w  = t >> 5, lane = t & 31;

    sHes[t] = g_hes[bi*NC + t];
    if (t < 64) sHi[t] = h[(b*NN + i)*64 + t];
    {
        const int j = t;
        const float xi0 = x[(b*NN+i)*3+0], xi1 = x[(b*NN+i)*3+1], xi2 = x[(b*NN+i)*3+2];
        const float dx = x[(b*NN+j)*3+0]-xi0;
        const float dy = x[(b*NN+j)*3+1]-xi1;
        const float dz = x[(b*NN+j)*3+2]-xi2;
        const float ssq = dx*dx + dy*dy + dz*dz;
        const float dd  = sqrtf(fmaxf(ssq, 0.f) + 1e-5f);
        const float inv = 1.f/(dd + 1e-5f);
        sXh[j*4+0] = dx*inv; sXh[j*4+1] = dy*inv; sXh[j*4+2] = dz*inv;
    }
    __syncthreads();

    float a0 = 0.f, a1 = 0.f, a2 = 0.f;
    for (int tile = 0; tile < 8; tile++) {
        {
            const float4* gd = (const float4*)(g_D + ((size_t)bi*NN + tile*32)*NC);
            #pragma unroll
            for (int it = 0; it < 8; it++) {
                const int l = t + it*256;
                const int row = l >> 6, c4 = l & 63;
                *(float4*)(sStage + row*256 + c4*4) = gd[row*64 + c4];
            }
        }
        __syncthreads();
        #pragma unroll 8
        for (int r = 0; r < 32; r++) {
            const int j = tile*32 + r;
            const float tvv = tanhap(sStage[r*256 + t]);
            a0 += tvv * sXh[j*4+0];
            a1 += tvv * sXh[j*4+1];
            a2 += tvv * sXh[j*4+2];
        }
        __syncthreads();
    }
    sComb[t*3+0] = a0*(1.f/NN);
    sComb[t*3+1] = a1*(1.f/NN);
    sComb[t*3+2] = a2*(1.f/NN);
    __syncthreads();

    {
        const float c0 = sComb[t*3+0], c1 = sComb[t*3+1], c2 = sComb[t*3+2];
        sCn[t] = c0*c0 + c1*c1 + c2*c2;
    }
    __syncthreads();
    if (t < 64) {
        float a = b_p1[t];
        for (int c = 0; c < 256; c++) a += sCn[c]*W_p1[c*64 + t];
        sT1[t] = siluf(a);
    }
    __syncthreads();
    if (t < 64) {
        float a = b_p2[t];
        for (int c = 0; c < 64; c++) a += sT1[c]*W_p2[c*64 + t];
        sT2[t] = siluf(a);
    }
    __syncthreads();
    if (t < 64) {
        float a = b_n1[t];
        for (int r = 0; r < 64;  r++) a += sHi[r] *W_n1[r*64 + t];
        for (int r = 0; r < 256; r++) a += sHes[r]*W_n1[(64+r)*64 + t];
        for (int r = 0; r < 64;  r++) a += sT2[r] *W_n1[(320+r)*64 + t];
        sT1[t] = siluf(a);
    }
    __syncthreads();
    if (t < 64) {
        float a = b_n2[t];
        for (int c = 0; c < 64; c++) a += sT1[c]*W_n2[c*64 + t];
        const float hn = sHi[t] + siluf(a);
        sHn[t] = hn;
        out[(b*NN + i)*64 + t] = hn;
    }
    __syncthreads();
    if (t < 64) {
        float a = b_v1[t];
        for (int c = 0; c < 64; c++) a += sHn[c]*W_v1[c*64 + t];
        sT1[t] = siluf(a);
    }
    __syncthreads();
    if (w == 0) {
        float s = sT1[lane]*W_v2[lane] + sT1[lane+32]*W_v2[lane+32];
        #pragma unroll
        for (int o = 16; o; o >>= 1) s += __shfl_xor_sync(~0u, s, o);
        if (lane == 0) sMisc[0] = 2.f/(1.f + __expf(-s));
    }
    if (w >= 1 && w <= 3) {
        const int dd = w - 1;
        float s = 0.f;
        for (int q2 = 0; q2 < 8; q2++)
            s += sComb[(lane + 32*q2)*3 + dd]*W_vmix[lane + 32*q2];
        #pragma unroll
        for (int o = 16; o; o >>= 1) s += __shfl_xor_sync(~0u, s, o);
        if (lane == 0) sMisc[1+dd] = s;
    }
    __syncthreads();
    if (t < 3) {
        const float vn = sMisc[1+t] + sMisc[0]*v[(b*NN+i)*3 + t];
        const float xn = x[(b*NN+i)*3 + t] + vn;
        out[NB*NN*64 + (b*NN+i)*3 + t]           = xn;
        out[NB*NN*64 + NB*NN*3 + (b*NN+i)*3 + t] = vn;
    }
}

// ---------------------------------------------------------------------------
extern "C" void kernel_launch(void* const* d_in, const int* in_sizes, int n_in,
                              void* d_out, int out_size)
{
    const float* h      = (const float*)d_in[0];
    const float* x      = (const float*)d_in[1];
    const float* v      = (const float*)d_in[2];
    const float* W_in   = (const float*)d_in[3];
    const float* b_in   = (const float*)d_in[4];
    const float* means  = (const float*)d_in[5];
    const float* betas  = (const float*)d_in[6];
    const float* W_o1   = (const float*)d_in[7];
    const float* b_o1   = (const float*)d_in[8];
    const float* W_o2   = (const float*)d_in[9];
    const float* b_o2   = (const float*)d_in[10];
    const float* W_sem  = (const float*)d_in[11];
    const float* b_sem  = (const float*)d_in[12];
    const float* W_xmix = (const float*)d_in[13];
    const float* W_p1   = (const float*)d_in[14];
    const float* b_p1   = (const float*)d_in[15];
    const float* W_p2   = (const float*)d_in[16];
    const float* b_p2   = (const float*)d_in[17];
    const float* W_n1   = (const float*)d_in[18];
    const float* b_n1   = (const float*)d_in[19];
    const float* W_n2   = (const float*)d_in[20];
    const float* b_n2   = (const float*)d_in[21];
    const float* W_v1   = (const float*)d_in[22];
    const float* b_v1   = (const float*)d_in[23];
    const float* W_v2   = (const float*)d_in[24];
    const float* W_vmix = (const float*)d_in[25];
    float* out = (float*)d_out;

    const size_t smE = (size_t)(51*64 + 4096 + 256 + 3*NKF + 2*64 + 8 + 2*64
                                + NN*3 + 4*NN + 16 + NN*65 + NN*4 + 32) * sizeof(float);
    const size_t smG = (size_t)(2*128*GLA + 2*64*GLB) * sizeof(__nv_bfloat16);
    const size_t smR = (size_t)(32*256 + 1024 + 768 + 256 + 4*64 + 16) * sizeof(float);

    cudaFuncSetAttribute(k_edge,   cudaFuncAttributeMaxDynamicSharedMemorySize, (int)smE);
    cudaFuncSetAttribute(k_gemm,   cudaFuncAttributeMaxDynamicSharedMemorySize, (int)smG);
    cudaFuncSetAttribute(k_reduce, cudaFuncAttributeMaxDynamicSharedMemorySize, (int)smR);

    k_prep<<<NC, NC>>>(W_xmix);
    k_pre2<<<NB*NN, 128>>>(h, W_in, W_o1);
    k_edge<<<NB*NN, 256, smE>>>(x, b_in, means, betas,
                                W_o1, b_o1, W_o2, b_o2, W_sem, b_sem);
    k_gemm<<<2048, 256, smG>>>();
    k_reduce<<<NB*NN, 256, smR>>>(h, x, v, W_p1, b_p1, W_p2, b_p2,
                                  W_n1, b_n1, W_n2, b_n2, W_v1, b_v1,
                                  W_v2, W_vmix, out);
}

// round 14
// speedup vs baseline: 1.3716x; 1.0471x over previous
#include <cuda_runtime.h>
#include <cuda_bf16.h>
#include <mma.h>
#include <math.h>
#include <stdint.h>

using namespace nvcuda;

#define NB   2
#define NN   256
#define NF   64
#define NKF  50
#define NC   256
#define DCAT 179   // 2F + KF + 1

// scratch (static device memory; allocation-free)
__device__ __nv_bfloat16 g_Uhi[(size_t)NB*NN*NN*NC];  // [row=bi*256+j][c'] hi
__device__ __nv_bfloat16 g_Ulo[(size_t)NB*NN*NN*NC];  // lo
__device__ __nv_bfloat16 g_Bhi[NC*NC];                // permuted W_xmix hi [k][n]
__device__ __nv_bfloat16 g_Blo[NC*NC];                // lo
__device__ float g_D[(size_t)NB*NN*NN*NC];            // GEMM output (134MB)
__device__ float g_hes[NB*NN*NC];                     // [bi][c] c=f*4+hd
__device__ float g_hw1[NB*NN*NKF];                    // h @ W_in[0:64]
__device__ float g_hw2[NB*NN*NKF];                    // h @ W_in[64:128]
__device__ float g_P1[NB*NN*64];                      // h @ W_o1[0:64]
__device__ float g_P2[NB*NN*64];                      // h @ W_o1[64:128]

__device__ __forceinline__ float siluf(float v){ return v / (1.f + __expf(-v)); }
__device__ __forceinline__ float tanhap(float x){
    float y; asm("tanh.approx.f32 %0, %1;" : "=f"(y) : "f"(x)); return y;
}
__device__ __forceinline__ void bf16split(float x, __nv_bfloat16& hi, __nv_bfloat16& lo){
    hi = __float2bfloat16(x);
    lo = __float2bfloat16(x - __bfloat162float(hi));
}

// ---------------------------------------------------------------------------
// Prep 1: split + row-permute W_xmix into bf16 hi/lo.
// ---------------------------------------------------------------------------
__global__ void k_prep(const float* __restrict__ W_xmix) {
    const int kk = blockIdx.x, c = threadIdx.x;
    const int grow = ((kk & 63) << 2) + (kk >> 6);
    __nv_bfloat16 hi, lo;
    bf16split(W_xmix[grow*NC + c], hi, lo);
    g_Bhi[kk*NC + c] = hi;
    g_Blo[kk*NC + c] = lo;
}

// ---------------------------------------------------------------------------
// Prep 2: per-node precomputes hw1/hw2 (h@W_in halves) and P1/P2 (h@W_o1
// halves). One block per node row, 128 threads.
// ---------------------------------------------------------------------------
__global__ __launch_bounds__(128) void k_pre2(
    const float* __restrict__ h, const float* __restrict__ W_in,
    const float* __restrict__ W_o1)
{
    __shared__ float sh[64];
    const int row = blockIdx.x;   // 0..NB*NN-1
    const int t = threadIdx.x;
    if (t < 64) sh[t] = h[row*64 + t];
    __syncthreads();
    if (t < 64) {
        float p1 = 0.f, p2 = 0.f;
        #pragma unroll 8
        for (int f = 0; f < 64; f++) {
            p1 += sh[f]*W_o1[f*64 + t];
            p2 += sh[f]*W_o1[(64+f)*64 + t];
        }
        g_P1[row*64 + t] = p1;
        g_P2[row*64 + t] = p2;
    } else if (t < 64 + NKF) {
        const int k = t - 64;
        float w1 = 0.f, w2 = 0.f;
        #pragma unroll 8
        for (int f = 0; f < 64; f++) {
            w1 += sh[f]*W_in[f*NKF + k];
            w2 += sh[f]*W_in[(64+f)*NKF + k];
        }
        g_hw1[row*NKF + k] = w1;
        g_hw2[row*NKF + k] = w2;
    }
}

// ---------------------------------------------------------------------------
// Kernel A: factorized edge MLP. One block per (b,i), thread j per pair.
// NO min-blocks clause: needs ~250 regs (tv[64]+he[64] live) — 128-reg cap
// caused massive spills in R12.
// ---------------------------------------------------------------------------
__global__ __launch_bounds__(256) void k_edge(
    const float* __restrict__ x,
    const float* __restrict__ b_in,
    const float* __restrict__ means, const float* __restrict__ betas,
    const float* __restrict__ W_o1,  const float* __restrict__ b_o1,
    const float* __restrict__ W_o2,  const float* __restrict__ b_o2,
    const float* __restrict__ W_sem, const float* __restrict__ b_sem)
{
    extern __shared__ __align__(32) float sm[];
    float* sWo1r = sm;                 // 51*64 = 3264 (rows 128..178)
    float* sWo2  = sWo1r + 51*64;      // 4096
    float* sWsem = sWo2 + 4096;        // 256
    float* sbin  = sWsem + 256;        // 50
    float* smean = sbin + NKF;         // 50
    float* sbeta = smean + NKF;        // 50
    float* sbo1  = sbeta + NKF;        // 64
    float* sbo2  = sbo1 + 64;          // 64
    float* sbsem = sbo2 + 64;          // 8
    float* sP2   = sbsem + 8;          // 64
    float* shw2  = sP2 + 64;           // 64 (50 used)
    float* sx    = shw2 + 64;          // 768
    float* sLog  = sx + NN*3;          // 1024
    float* sRed  = sLog + 4*NN;        // 16
    float* sHeMat= sRed + 16;          // 256*65 = 16640
    float* sAttS = sHeMat + 16640;     // 1024

    const int t  = threadIdx.x;
    const int bi = blockIdx.x;
    const int b  = bi >> 8;
    const int i  = bi & 255;

    for (int l = t; l < 51*64; l += 256) sWo1r[l] = W_o1[128*64 + l];
    for (int l = t; l < 4096;  l += 256) sWo2[l] = W_o2[l];
    sWsem[t] = W_sem[t];
    if (t < NKF) { sbin[t]=b_in[t]; smean[t]=means[t]; sbeta[t]=betas[t]; }
    if (t < 64)  { sbo1[t]=b_o1[t]; sbo2[t]=b_o2[t];
                   sP2[t] = g_P2[(b*NN+i)*64 + t]; }
    if (t < NKF) shw2[t] = g_hw2[(b*NN+i)*NKF + t];
    if (t < 4)   sbsem[t]=b_sem[t];
    for (int l = t; l < NN*3; l += 256) sx[l] = x[b*NN*3 + l];
    __syncthreads();

    const int j = t;
    const float dx = sx[j*3+0]-sx[i*3+0];
    const float dy = sx[j*3+1]-sx[i*3+1];
    const float dz = sx[j*3+2]-sx[i*3+2];
    const float ss = dx*dx + dy*dy + dz*dz;
    const float d  = sqrtf(fmaxf(ss, 0.f) + 1e-5f);
    const float em  = __expf(-d);
    const float cut = (d < 5.f) ? 0.5f*(__cosf(d*0.6283185307179586f)+1.f) : 0.f;

    // --- tv init: P1[j] + P2[i] + b_o1 + d * W_o1[178] ---
    float tv[64];
    {
        const float4* p1r = (const float4*)(g_P1 + (b*NN+j)*64);
        const float4* dr  = (const float4*)(sWo1r + 50*64);
        #pragma unroll
        for (int q = 0; q < 16; q++) {
            float4 p = p1r[q];
            float4 w = dr[q];
            tv[4*q+0] = p.x + sP2[4*q+0] + sbo1[4*q+0] + d*w.x;
            tv[4*q+1] = p.y + sP2[4*q+1] + sbo1[4*q+1] + d*w.y;
            tv[4*q+2] = p.z + sP2[4*q+2] + sbo1[4*q+2] + d*w.z;
            tv[4*q+3] = p.w + sP2[4*q+3] + sbo1[4*q+3] + d*w.w;
        }
    }
    // --- rbf terms, fused (no rh array) ---
    {
        const float* hw1r = g_hw1 + (b*NN+j)*NKF;
        #pragma unroll 2
        for (int k = 0; k < NKF; k++) {
            const float h1 = hw1r[k] + shw2[k] + sbin[k];
            const float dm = em - smean[k];
            const float rh = cut * __expf(-sbeta[k]*dm*dm) * h1;
            const float4* r4 = (const float4*)(sWo1r + k*64);
            #pragma unroll
            for (int q = 0; q < 16; q++) {
                float4 w = r4[q];
                tv[4*q+0] += rh*w.x; tv[4*q+1] += rh*w.y;
                tv[4*q+2] += rh*w.z; tv[4*q+3] += rh*w.w;
            }
        }
    }
    #pragma unroll
    for (int k = 0; k < 64; k++) tv[k] = siluf(tv[k]);

    // --- he = tv @ W_o2 + b_o2 ---
    float he[64];
    #pragma unroll
    for (int k = 0; k < 64; k++) he[k] = sbo2[k];
    #pragma unroll
    for (int c = 0; c < 64; c++) {
        const float val = tv[c];
        const float4* r4 = (const float4*)(sWo2 + c*64);
        #pragma unroll
        for (int q = 0; q < 16; q++) {
            float4 w = r4[q];
            he[4*q+0] += val*w.x; he[4*q+1] += val*w.y;
            he[4*q+2] += val*w.z; he[4*q+3] += val*w.w;
        }
    }

    // --- semantic logits + celu(alpha=2) + self-mask ---
    float l0=sbsem[0], l1=sbsem[1], l2=sbsem[2], l3=sbsem[3];
    #pragma unroll
    for (int f = 0; f < 64; f++) {
        const float v4 = he[f];
        l0 += v4*sWsem[f*4+0]; l1 += v4*sWsem[f*4+1];
        l2 += v4*sWsem[f*4+2]; l3 += v4*sWsem[f*4+3];
    }
    float lg[4] = {l0, l1, l2, l3};
    #pragma unroll
    for (int hd = 0; hd < 4; hd++) {
        float a = lg[hd];
        a = (a > 0.f) ? a : 2.f*(__expf(0.5f*a) - 1.f);
        if (j == i) a -= 1e5f;
        sLog[hd*NN + j] = a;
    }
    #pragma unroll
    for (int f = 0; f < 64; f++) sHeMat[j*65 + f] = he[f];
    __syncthreads();

    // --- softmax over j, one warp per head ---
    const int wp = t >> 5, lane = t & 31;
    if (wp < 4) {
        float m = -1e30f;
        for (int q = 0; q < 8; q++) m = fmaxf(m, sLog[wp*NN + lane + 32*q]);
        #pragma unroll
        for (int o = 16; o; o >>= 1) m = fmaxf(m, __shfl_xor_sync(~0u, m, o));
        float s = 0.f;
        for (int q = 0; q < 8; q++) s += __expf(sLog[wp*NN + lane + 32*q] - m);
        #pragma unroll
        for (int o = 16; o; o >>= 1) s += __shfl_xor_sync(~0u, s, o);
        if (lane == 0) { sRed[wp*2] = m; sRed[wp*2+1] = s; }
    }
    __syncthreads();

    float att4[4];
    #pragma unroll
    for (int hd = 0; hd < 4; hd++) {
        att4[hd] = __expf(sLog[hd*NN + j] - sRed[hd*2]) / sRed[hd*2+1];
        sAttS[j*4 + hd] = att4[hd];
    }
    // write U row (c' = hd*64 + f) as bf16 hi/lo
    {
        __nv_bfloat162* uh = (__nv_bfloat162*)(g_Uhi + ((size_t)bi*NN + j)*NC);
        __nv_bfloat162* ul = (__nv_bfloat162*)(g_Ulo + ((size_t)bi*NN + j)*NC);
        #pragma unroll
        for (int c2 = 0; c2 < 128; c2++) {
            const int i0 = 2*c2;
            const float u0 = att4[(i0+0)>>6] * he[(i0+0)&63];
            const float u1 = att4[(i0+1)>>6] * he[(i0+1)&63];
            __nv_bfloat16 h0, l0b, h1b, l1b;
            bf16split(u0, h0, l0b);
            bf16split(u1, h1b, l1b);
            uh[c2] = __nv_bfloat162(h0, h1b);
            ul[c2] = __nv_bfloat162(l0b, l1b);
        }
    }
    __syncthreads();

    // --- h_e column sums (c = f*4 + hd) ---
    {
        const int f = t >> 2, hd = t & 3;
        float s = 0.f;
        for (int jj = 0; jj < NN; jj++) s += sHeMat[jj*65 + f] * sAttS[jj*4 + hd];
        g_hes[bi*NC + t] = s;
    }
}

// ---------------------------------------------------------------------------
// Kernel B: ONE big GEMM  D[131072,256] = U @ W' (R9/R12 version).
// ---------------------------------------------------------------------------
#define GLA 72
#define GLB 136

__global__ __launch_bounds__(256, 2) void k_gemm()
{
    extern __shared__ __align__(16) char gsm[];
    __nv_bfloat16* sAhi = (__nv_bfloat16*)gsm;      // 128*72
    __nv_bfloat16* sAlo = sAhi + 128*GLA;
    __nv_bfloat16* sBhi = sAlo + 128*GLA;           // 64*136
    __nv_bfloat16* sBlo = sBhi + 64*GLB;

    const int t    = threadIdx.x;
    const int mblk = blockIdx.x >> 1;
    const int nblk = blockIdx.x & 1;
    const int w    = t >> 5;
    const int wm   = w & 3;
    const int wn2  = w >> 2;

    wmma::fragment<wmma::accumulator,16,16,16,float> acc[2][4];
    #pragma unroll
    for (int mi = 0; mi < 2; mi++)
        #pragma unroll
        for (int ni = 0; ni < 4; ni++) wmma::fill_fragment(acc[mi][ni], 0.f);

    for (int kc = 0; kc < 4; kc++) {
        {
            const size_t gb = ((size_t)mblk*128)*NC + kc*64;
            #pragma unroll
            for (int it = 0; it < 4; it++) {
                const int l = t + it*256;
                const int row = l >> 3, c8 = l & 7;
                *(uint4*)(sAhi + row*GLA + c8*8) = *(const uint4*)(g_Uhi + gb + (size_t)row*NC + c8*8);
                *(uint4*)(sAlo + row*GLA + c8*8) = *(const uint4*)(g_Ulo + gb + (size_t)row*NC + c8*8);
            }
        }
        {
            const int gb = (kc*64)*NC + nblk*128;
            #pragma unroll
            for (int it = 0; it < 4; it++) {
                const int l = t + it*256;
                const int row = l >> 4, c8 = l & 15;
                *(uint4*)(sBhi + row*GLB + c8*8) = *(const uint4*)(g_Bhi + gb + row*NC + c8*8);
                *(uint4*)(sBlo + row*GLB + c8*8) = *(const uint4*)(g_Blo + gb + row*NC + c8*8);
            }
        }
        __syncthreads();

        #pragma unroll
        for (int ks = 0; ks < 4; ks++) {
            wmma::fragment<wmma::matrix_a,16,16,16,__nv_bfloat16,wmma::row_major> ah[2], al[2];
            #pragma unroll
            for (int mi = 0; mi < 2; mi++) {
                wmma::load_matrix_sync(ah[mi], sAhi + (wm*32 + mi*16)*GLA + ks*16, GLA);
                wmma::load_matrix_sync(al[mi], sAlo + (wm*32 + mi*16)*GLA + ks*16, GLA);
            }
            #pragma unroll
            for (int ni = 0; ni < 4; ni++) {
                wmma::fragment<wmma::matrix_b,16,16,16,__nv_bfloat16,wmma::row_major> bh, bl;
                wmma::load_matrix_sync(bh, sBhi + (ks*16)*GLB + wn2*64 + ni*16, GLB);
                wmma::load_matrix_sync(bl, sBlo + (ks*16)*GLB + wn2*64 + ni*16, GLB);
                #pragma unroll
                for (int mi = 0; mi < 2; mi++) {
                    wmma::mma_sync(acc[mi][ni], ah[mi], bh, acc[mi][ni]);
                    wmma::mma_sync(acc[mi][ni], ah[mi], bl, acc[mi][ni]);
                    wmma::mma_sync(acc[mi][ni], al[mi], bh, acc[mi][ni]);
                }
            }
        }
        __syncthreads();
    }

    #pragma unroll
    for (int mi = 0; mi < 2; mi++)
        #pragma unroll
        for (int ni = 0; ni < 4; ni++) {
            float* dst = g_D + ((size_t)mblk*128 + wm*32 + mi*16)*NC
                             + nblk*128 + wn2*64 + ni*16;
            wmma::store_matrix_sync(dst, acc[mi][ni], NC, wmma::mem_row_major);
        }
}

// ---------------------------------------------------------------------------
// Kernel C: tanh + xhat-weighted j-reduction over D + full node tail.
// ---------------------------------------------------------------------------
__global__ __launch_bounds__(256, 1) void k_reduce(
    const float* __restrict__ h,    const float* __restrict__ x,
    const float* __restrict__ v,
    const float* __restrict__ W_p1, const float* __restrict__ b_p1,
    const float* __restrict__ W_p2, const float* __restrict__ b_p2,
    const float* __restrict__ W_n1, const float* __restrict__ b_n1,
    const float* __restrict__ W_n2, const float* __restrict__ b_n2,
    const float* __restrict__ W_v1, const float* __restrict__ b_v1,
    const float* __restrict__ W_v2, const float* __restrict__ W_vmix,
    float* __restrict__ out)
{
    extern __shared__ __align__(16) float rsm[];
    float* sStage = rsm;               // 32*256
    float* sXh    = sStage + 32*256;   // 1024
    float* sComb  = sXh + 1024;        // 768
    float* sHes   = sComb + 768;       // 256
    float* sHi    = sHes + 256;        // 64
    float* sT1    = sHi + 64;          // 64
    float* sT2    = sT1 + 64;          // 64
    float* sHn    = sT2 + 64;          // 64
    float* sMisc  = sHn + 64;          // 16
    float* sCn    = sStage;            // alias after staging done

    const int t  = threadIdx.x;
    const int bi = blockIdx.x;
    const int b  = bi >> 8;
    const int i  = bi & 255;
    const int w  = t >> 5, lane = t & 31;

    sHes[t] = g_hes[bi*NC + t];
    if (t < 64) sHi[t] = h[(b*NN + i)*64 + t];
    {
        const int j = t;
        const float xi0 = x[(b*NN+i)*3+0], xi1 = x[(b*NN+i)*3+1], xi2 = x[(b*NN+i)*3+2];
        const float dx = x[(b*NN+j)*3+0]-xi0;
        const float dy = x[(b*NN+j)*3+1]-xi1;
        const float dz = x[(b*NN+j)*3+2]-xi2;
        const float ssq = dx*dx + dy*dy + dz*dz;
        const float dd  = sqrtf(fmaxf(ssq, 0.f) + 1e-5f);
        const float inv = 1.f/(dd + 1e-5f);
        sXh[j*4+0] = dx*inv; sXh[j*4+1] = dy*inv; sXh[j*4+2] = dz*inv;
    }
    __syncthreads();

    float a0 = 0.f, a1 = 0.f, a2 = 0.f;
    for (int tile = 0; tile < 8; tile++) {
        {
            const float4* gd = (const float4*)(g_D + ((size_t)bi*NN + tile*32)*NC);
            #pragma unroll
            for (int it = 0; it < 8; it++) {
                const int l = t + it*256;
                const int row = l >> 6, c4 = l & 63;
                *(float4*)(sStage + row*256 + c4*4) = gd[row*64 + c4];
            }
        }
        __syncthreads();
        #pragma unroll 8
        for (int r = 0; r < 32; r++) {
            const int j = tile*32 + r;
            const float tvv = tanhap(sStage[r*256 + t]);
            a0 += tvv * sXh[j*4+0];
            a1 += tvv * sXh[j*4+1];
            a2 += tvv * sXh[j*4+2];
        }
        __syncthreads();
    }
    sComb[t*3+0] = a0*(1.f/NN);
    sComb[t*3+1] = a1*(1.f/NN);
    sComb[t*3+2] = a2*(1.f/NN);
    __syncthreads();

    {
        const float c0 = sComb[t*3+0], c1 = sComb[t*3+1], c2 = sComb[t*3+2];
        sCn[t] = c0*c0 + c1*c1 + c2*c2;
    }
    __syncthreads();
    if (t < 64) {
        float a = b_p1[t];
        for (int c = 0; c < 256; c++) a += sCn[c]*W_p1[c*64 + t];
        sT1[t] = siluf(a);
    }
    __syncthreads();
    if (t < 64) {
        float a = b_p2[t];
        for (int c = 0; c < 64; c++) a += sT1[c]*W_p2[c*64 + t];
        sT2[t] = siluf(a);
    }
    __syncthreads();
    if (t < 64) {
        float a = b_n1[t];
        for (int r = 0; r < 64;  r++) a += sHi[r] *W_n1[r*64 + t];
        for (int r = 0; r < 256; r++) a += sHes[r]*W_n1[(64+r)*64 + t];
        for (int r = 0; r < 64;  r++) a += sT2[r] *W_n1[(320+r)*64 + t];
        sT1[t] = siluf(a);
    }
    __syncthreads();
    if (t < 64) {
        float a = b_n2[t];
        for (int c = 0; c < 64; c++) a += sT1[c]*W_n2[c*64 + t];
        const float hn = sHi[t] + siluf(a);
        sHn[t] = hn;
        out[(b*NN + i)*64 + t] = hn;
    }
    __syncthreads();
    if (t < 64) {
        float a = b_v1[t];
        for (int c = 0; c < 64; c++) a += sHn[c]*W_v1[c*64 + t];
        sT1[t] = siluf(a);
    }
    __syncthreads();
    if (w == 0) {
        float s = sT1[lane]*W_v2[lane] + sT1[lane+32]*W_v2[lane+32];
        #pragma unroll
        for (int o = 16; o; o >>= 1) s += __shfl_xor_sync(~0u, s, o);
        if (lane == 0) sMisc[0] = 2.f/(1.f + __expf(-s));
    }
    if (w >= 1 && w <= 3) {
        const int dd = w - 1;
        float s = 0.f;
        for (int q2 = 0; q2 < 8; q2++)
            s += sComb[(lane + 32*q2)*3 + dd]*W_vmix[lane + 32*q2];
        #pragma unroll
        for (int o = 16; o; o >>= 1) s += __shfl_xor_sync(~0u, s, o);
        if (lane == 0) sMisc[1+dd] = s;
    }
    __syncthreads();
    if (t < 3) {
        const float vn = sMisc[1+t] + sMisc[0]*v[(b*NN+i)*3 + t];
        const float xn = x[(b*NN+i)*3 + t] + vn;
        out[NB*NN*64 + (b*NN+i)*3 + t]           = xn;
        out[NB*NN*64 + NB*NN*3 + (b*NN+i)*3 + t] = vn;
    }
}

// ---------------------------------------------------------------------------
extern "C" void kernel_launch(void* const* d_in, const int* in_sizes, int n_in,
                              void* d_out, int out_size)
{
    const float* h      = (const float*)d_in[0];
    const float* x      = (const float*)d_in[1];
    const float* v      = (const float*)d_in[2];
    const float* W_in   = (const float*)d_in[3];
    const float* b_in   = (const float*)d_in[4];
    const float* means  = (const float*)d_in[5];
    const float* betas  = (const float*)d_in[6];
    const float* W_o1   = (const float*)d_in[7];
    const float* b_o1   = (const float*)d_in[8];
    const float* W_o2   = (const float*)d_in[9];
    const float* b_o2   = (const float*)d_in[10];
    const float* W_sem  = (const float*)d_in[11];
    const float* b_sem  = (const float*)d_in[12];
    const float* W_xmix = (const float*)d_in[13];
    const float* W_p1   = (const float*)d_in[14];
    const float* b_p1   = (const float*)d_in[15];
    const float* W_p2   = (const float*)d_in[16];
    const float* b_p2   = (const float*)d_in[17];
    const float* W_n1   = (const float*)d_in[18];
    const float* b_n1   = (const float*)d_in[19];
    const float* W_n2   = (const float*)d_in[20];
    const float* b_n2   = (const float*)d_in[21];
    const float* W_v1   = (const float*)d_in[22];
    const float* b_v1   = (const float*)d_in[23];
    const float* W_v2   = (const float*)d_in[24];
    const float* W_vmix = (const float*)d_in[25];
    float* out = (float*)d_out;

    const size_t smE = (size_t)(51*64 + 4096 + 256 + 3*NKF + 2*64 + 8 + 2*64
                                + NN*3 + 4*NN + 16 + NN*65 + NN*4 + 32) * sizeof(float);
    const size_t smG = (size_t)(2*128*GLA + 2*64*GLB) * sizeof(__nv_bfloat16);
    const size_t smR = (size_t)(32*256 + 1024 + 768 + 256 + 4*64 + 16) * sizeof(float);

    cudaFuncSetAttribute(k_edge,   cudaFuncAttributeMaxDynamicSharedMemorySize, (int)smE);
    cudaFuncSetAttribute(k_gemm,   cudaFuncAttributeMaxDynamicSharedMemorySize, (int)smG);
    cudaFuncSetAttribute(k_reduce, cudaFuncAttributeMaxDynamicSharedMemorySize, (int)smR);

    k_prep<<<NC, NC>>>(W_xmix);
    k_pre2<<<NB*NN, 128>>>(h, W_in, W_o1);
    k_edge<<<NB*NN, 256, smE>>>(x, b_in, means, betas,
                                W_o1, b_o1, W_o2, b_o2, W_sem, b_sem);
    k_gemm<<<2048, 256, smG>>>();
    k_reduce<<<NB*NN, 256, smR>>>(h, x, v, W_p1, b_p1, W_p2, b_p2,
                                  W_n1, b_n1, W_n2, b_n2, W_v1, b_v1,
                                  W_v2, W_vmix, out);
}

// round 16
// speedup vs baseline: 1.4105x; 1.0283x over previous
#include <cuda_runtime.h>
#include <cuda_bf16.h>
#include <mma.h>
#include <math.h>
#include <stdint.h>

using namespace nvcuda;

#define NB   2
#define NN   256
#define NF   64
#define NKF  50
#define NC   256
#define DCAT 179   // 2F + KF + 1

// scratch (static device memory; allocation-free)
__device__ __nv_bfloat16 g_Uhi[(size_t)NB*NN*NN*NC];  // [row=bi*256+j][c'] hi
__device__ __nv_bfloat16 g_Ulo[(size_t)NB*NN*NN*NC];  // lo
__device__ __nv_bfloat16 g_Bhi[NC*NC];                // permuted W_xmix hi [k][n]
__device__ __nv_bfloat16 g_Blo[NC*NC];                // lo
__device__ float g_D[(size_t)NB*NN*NN*NC];            // GEMM output (134MB)
__device__ float g_hes[NB*NN*NC];                     // [bi][c] c=f*4+hd
__device__ float g_hw1[NB*NN*NKF];                    // h @ W_in[0:64]
__device__ float g_hw2[NB*NN*NKF];                    // h @ W_in[64:128]
__device__ float g_P1[NB*NN*64];                      // h @ W_o1[0:64]
__device__ float g_P2[NB*NN*64];                      // h @ W_o1[64:128]

__device__ __forceinline__ float siluf(float v){ return v / (1.f + __expf(-v)); }
__device__ __forceinline__ float tanhap(float x){
    float y; asm("tanh.approx.f32 %0, %1;" : "=f"(y) : "f"(x)); return y;
}
__device__ __forceinline__ void bf16split(float x, __nv_bfloat16& hi, __nv_bfloat16& lo){
    hi = __float2bfloat16(x);
    lo = __float2bfloat16(x - __bfloat162float(hi));
}

// ---------------------------------------------------------------------------
// Prep 1: split + row-permute W_xmix into bf16 hi/lo.
// ---------------------------------------------------------------------------
__global__ void k_prep(const float* __restrict__ W_xmix) {
    const int kk = blockIdx.x, c = threadIdx.x;
    const int grow = ((kk & 63) << 2) + (kk >> 6);
    __nv_bfloat16 hi, lo;
    bf16split(W_xmix[grow*NC + c], hi, lo);
    g_Bhi[kk*NC + c] = hi;
    g_Blo[kk*NC + c] = lo;
}

// ---------------------------------------------------------------------------
// Prep 2: per-node precomputes hw1/hw2 and P1/P2.
// ---------------------------------------------------------------------------
__global__ __launch_bounds__(128) void k_pre2(
    const float* __restrict__ h, const float* __restrict__ W_in,
    const float* __restrict__ W_o1)
{
    __shared__ float sh[64];
    const int row = blockIdx.x;
    const int t = threadIdx.x;
    if (t < 64) sh[t] = h[row*64 + t];
    __syncthreads();
    if (t < 64) {
        float p1 = 0.f, p2 = 0.f;
        #pragma unroll 8
        for (int f = 0; f < 64; f++) {
            p1 += sh[f]*W_o1[f*64 + t];
            p2 += sh[f]*W_o1[(64+f)*64 + t];
        }
        g_P1[row*64 + t] = p1;
        g_P2[row*64 + t] = p2;
    } else if (t < 64 + NKF) {
        const int k = t - 64;
        float w1 = 0.f, w2 = 0.f;
        #pragma unroll 8
        for (int f = 0; f < 64; f++) {
            w1 += sh[f]*W_in[f*NKF + k];
            w2 += sh[f]*W_in[(64+f)*NKF + k];
        }
        g_hw1[row*NKF + k] = w1;
        g_hw2[row*NKF + k] = w2;
    }
}

// ---------------------------------------------------------------------------
// Kernel A v3: factorized edge MLP, 512 threads: thread (j, half) owns 32
// of 64 channels. tv crosses threads via shared. 16 warps/SM for latency.
// ---------------------------------------------------------------------------
__global__ __launch_bounds__(512) void k_edge(
    const float* __restrict__ x,
    const float* __restrict__ b_in,
    const float* __restrict__ means, const float* __restrict__ betas,
    const float* __restrict__ W_o1,  const float* __restrict__ b_o1,
    const float* __restrict__ W_o2,  const float* __restrict__ b_o2,
    const float* __restrict__ W_sem, const float* __restrict__ b_sem)
{
    extern __shared__ __align__(32) float sm[];
    float* sWo1r = sm;                 // 51*64 = 3264
    float* sWo2  = sWo1r + 51*64;      // 4096
    float* sWsem = sWo2 + 4096;        // 256
    float* sbin  = sWsem + 256;        // 50
    float* smean = sbin + NKF;         // 50
    float* sbeta = smean + NKF;        // 50
    float* sbo1  = sbeta + NKF;        // 64
    float* sbo2  = sbo1 + 64;          // 64
    float* sbsem = sbo2 + 64;          // 8
    float* sP2   = sbsem + 8;          // 64
    float* shw2  = sP2 + 64;           // 64 (50 used)
    float* sx    = shw2 + 64;          // 768
    float* sLog  = sx + NN*3;          // 1024
    float* sRed  = sLog + 4*NN;        // 16
    float* sTv   = sRed + 16;          // 256*65 = 16640
    float* sHeMat= sTv + 16640;        // 256*65 = 16640
    float* sAttS = sHeMat + 16640;     // 1024

    const int t    = threadIdx.x;
    const int j    = t & 255;
    const int half = t >> 8;
    const int cb   = half*32;          // channel base
    const int bi   = blockIdx.x;
    const int b    = bi >> 8;
    const int i    = bi & 255;

    for (int l = t; l < 51*64; l += 512) sWo1r[l] = W_o1[128*64 + l];
    for (int l = t; l < 4096;  l += 512) sWo2[l] = W_o2[l];
    if (t < 256) sWsem[t] = W_sem[t];
    if (t < NKF) { sbin[t]=b_in[t]; smean[t]=means[t]; sbeta[t]=betas[t]; }
    if (t < 64)  { sbo1[t]=b_o1[t]; sbo2[t]=b_o2[t];
                   sP2[t] = g_P2[(b*NN+i)*64 + t]; }
    if (t >= 64 && t < 64+NKF) shw2[t-64] = g_hw2[(b*NN+i)*NKF + (t-64)];
    if (t >= 128 && t < 132) sbsem[t-128] = b_sem[t-128];
    for (int l = t; l < NN*3; l += 512) sx[l] = x[b*NN*3 + l];
    __syncthreads();

    const float dx = sx[j*3+0]-sx[i*3+0];
    const float dy = sx[j*3+1]-sx[i*3+1];
    const float dz = sx[j*3+2]-sx[i*3+2];
    const float ss = dx*dx + dy*dy + dz*dz;
    const float d  = sqrtf(fmaxf(ss, 0.f) + 1e-5f);
    const float em  = __expf(-d);
    const float cut = (d < 5.f) ? 0.5f*(__cosf(d*0.6283185307179586f)+1.f) : 0.f;

    // --- tv (my 32 channels): P1[j] + P2[i] + b_o1 + d*W_o1[178] + rbf terms
    float tv[32];
    {
        const float4* p1r = (const float4*)(g_P1 + (b*NN+j)*64 + cb);
        const float4* dr  = (const float4*)(sWo1r + 50*64 + cb);
        #pragma unroll
        for (int q = 0; q < 8; q++) {
            float4 p = p1r[q];
            float4 w = dr[q];
            tv[4*q+0] = p.x + sP2[cb+4*q+0] + sbo1[cb+4*q+0] + d*w.x;
            tv[4*q+1] = p.y + sP2[cb+4*q+1] + sbo1[cb+4*q+1] + d*w.y;
            tv[4*q+2] = p.z + sP2[cb+4*q+2] + sbo1[cb+4*q+2] + d*w.z;
            tv[4*q+3] = p.w + sP2[cb+4*q+3] + sbo1[cb+4*q+3] + d*w.w;
        }
    }
    {
        const float* hw1r = g_hw1 + (b*NN+j)*NKF;
        #pragma unroll 2
        for (int k = 0; k < NKF; k++) {
            const float h1 = hw1r[k] + shw2[k] + sbin[k];
            const float dm = em - smean[k];
            const float rh = cut * __expf(-sbeta[k]*dm*dm) * h1;
            const float4* r4 = (const float4*)(sWo1r + k*64 + cb);
            #pragma unroll
            for (int q = 0; q < 8; q++) {
                float4 w = r4[q];
                tv[4*q+0] += rh*w.x; tv[4*q+1] += rh*w.y;
                tv[4*q+2] += rh*w.z; tv[4*q+3] += rh*w.w;
            }
        }
    }
    #pragma unroll
    for (int k = 0; k < 32; k++) sTv[j*65 + cb + k] = siluf(tv[k]);
    __syncthreads();

    // --- he (my 32 channels) = full tv row @ W_o2 + b_o2 ---
    float he[32];
    #pragma unroll
    for (int k = 0; k < 32; k++) he[k] = sbo2[cb + k];
    #pragma unroll 4
    for (int k = 0; k < 64; k++) {
        const float tvk = sTv[j*65 + k];
        const float4* r4 = (const float4*)(sWo2 + k*64 + cb);
        #pragma unroll
        for (int q = 0; q < 8; q++) {
            float4 w = r4[q];
            he[4*q+0] += tvk*w.x; he[4*q+1] += tvk*w.y;
            he[4*q+2] += tvk*w.z; he[4*q+3] += tvk*w.w;
        }
    }
    #pragma unroll
    for (int k = 0; k < 32; k++) sHeMat[j*65 + cb + k] = he[k];
    __syncthreads();

    // --- semantic logits from sHeMat (t < 256 handles row j=t) ---
    if (t < 256) {
        float l0=sbsem[0], l1=sbsem[1], l2=sbsem[2], l3=sbsem[3];
        #pragma unroll 8
        for (int f = 0; f < 64; f++) {
            const float v4 = sHeMat[t*65 + f];
            l0 += v4*sWsem[f*4+0]; l1 += v4*sWsem[f*4+1];
            l2 += v4*sWsem[f*4+2]; l3 += v4*sWsem[f*4+3];
        }
        float lg[4] = {l0, l1, l2, l3};
        #pragma unroll
        for (int hd = 0; hd < 4; hd++) {
            float a = lg[hd];
            a = (a > 0.f) ? a : 2.f*(__expf(0.5f*a) - 1.f);
            if (t == i) a -= 1e5f;
            sLog[hd*NN + t] = a;
        }
    }
    __syncthreads();

    // --- softmax over j, one warp per head ---
    const int wp = t >> 5, lane = t & 31;
    if (wp < 4) {
        float m = -1e30f;
        for (int q = 0; q < 8; q++) m = fmaxf(m, sLog[wp*NN + lane + 32*q]);
        #pragma unroll
        for (int o = 16; o; o >>= 1) m = fmaxf(m, __shfl_xor_sync(~0u, m, o));
        float s = 0.f;
        for (int q = 0; q < 8; q++) s += __expf(sLog[wp*NN + lane + 32*q] - m);
        #pragma unroll
        for (int o = 16; o; o >>= 1) s += __shfl_xor_sync(~0u, s, o);
        if (lane == 0) { sRed[wp*2] = m; sRed[wp*2+1] = s; }
    }
    __syncthreads();

    float att4[4];
    #pragma unroll
    for (int hd = 0; hd < 4; hd++) {
        att4[hd] = __expf(sLog[hd*NN + j] - sRed[hd*2]) / sRed[hd*2+1];
        if (half == 0) sAttS[j*4 + hd] = att4[hd];
    }
    // --- write U row segments (c' = hd*64 + f, f in [cb, cb+32)) ---
    {
        #pragma unroll
        for (int hd = 0; hd < 4; hd++) {
            const float a = att4[hd];
            __nv_bfloat162* uh = (__nv_bfloat162*)(g_Uhi + ((size_t)bi*NN + j)*NC + hd*64 + cb);
            __nv_bfloat162* ul = (__nv_bfloat162*)(g_Ulo + ((size_t)bi*NN + j)*NC + hd*64 + cb);
            #pragma unroll
            for (int c2 = 0; c2 < 16; c2++) {
                const float u0 = a * he[2*c2+0];
                const float u1 = a * he[2*c2+1];
                __nv_bfloat16 h0, l0b, h1b, l1b;
                bf16split(u0, h0, l0b);
                bf16split(u1, h1b, l1b);
                uh[c2] = __nv_bfloat162(h0, h1b);
                ul[c2] = __nv_bfloat162(l0b, l1b);
            }
        }
    }
    __syncthreads();

    // --- h_e column sums (c = f*4 + hd), t < 256 ---
    if (t < 256) {
        const int f = t >> 2, hd = t & 3;
        float s = 0.f;
        #pragma unroll 8
        for (int jj = 0; jj < NN; jj++) s += sHeMat[jj*65 + f] * sAttS[jj*4 + hd];
        g_hes[bi*NC + t] = s;
    }
}

// ---------------------------------------------------------------------------
// Kernel B: ONE big GEMM  D[131072,256] = U @ W' (unchanged; near HMMA ceiling).
// ---------------------------------------------------------------------------
#define GLA 72
#define GLB 136

__global__ __launch_bounds__(256, 2) void k_gemm()
{
    extern __shared__ __align__(16) char gsm[];
    __nv_bfloat16* sAhi = (__nv_bfloat16*)gsm;      // 128*72
    __nv_bfloat16* sAlo = sAhi + 128*GLA;
    __nv_bfloat16* sBhi = sAlo + 128*GLA;           // 64*136
    __nv_bfloat16* sBlo = sBhi + 64*GLB;

    const int t    = threadIdx.x;
    const int mblk = blockIdx.x >> 1;
    const int nblk = blockIdx.x & 1;
    const int w    = t >> 5;
    const int wm   = w & 3;
    const int wn2  = w >> 2;

    wmma::fragment<wmma::accumulator,16,16,16,float> acc[2][4];
    #pragma unroll
    for (int mi = 0; mi < 2; mi++)
        #pragma unroll
        for (int ni = 0; ni < 4; ni++) wmma::fill_fragment(acc[mi][ni], 0.f);

    for (int kc = 0; kc < 4; kc++) {
        {
            const size_t gb = ((size_t)mblk*128)*NC + kc*64;
            #pragma unroll
            for (int it = 0; it < 4; it++) {
                const int l = t + it*256;
                const int row = l >> 3, c8 = l & 7;
                *(uint4*)(sAhi + row*GLA + c8*8) = *(const uint4*)(g_Uhi + gb + (size_t)row*NC + c8*8);
                *(uint4*)(sAlo + row*GLA + c8*8) = *(const uint4*)(g_Ulo + gb + (size_t)row*NC + c8*8);
            }
        }
        {
            const int gb = (kc*64)*NC + nblk*128;
            #pragma unroll
            for (int it = 0; it < 4; it++) {
                const int l = t + it*256;
                const int row = l >> 4, c8 = l & 15;
                *(uint4*)(sBhi + row*GLB + c8*8) = *(const uint4*)(g_Bhi + gb + row*NC + c8*8);
                *(uint4*)(sBlo + row*GLB + c8*8) = *(const uint4*)(g_Blo + gb + row*NC + c8*8);
            }
        }
        __syncthreads();

        #pragma unroll
        for (int ks = 0; ks < 4; ks++) {
            wmma::fragment<wmma::matrix_a,16,16,16,__nv_bfloat16,wmma::row_major> ah[2], al[2];
            #pragma unroll
            for (int mi = 0; mi < 2; mi++) {
                wmma::load_matrix_sync(ah[mi], sAhi + (wm*32 + mi*16)*GLA + ks*16, GLA);
                wmma::load_matrix_sync(al[mi], sAlo + (wm*32 + mi*16)*GLA + ks*16, GLA);
            }
            #pragma unroll
            for (int ni = 0; ni < 4; ni++) {
                wmma::fragment<wmma::matrix_b,16,16,16,__nv_bfloat16,wmma::row_major> bh, bl;
                wmma::load_matrix_sync(bh, sBhi + (ks*16)*GLB + wn2*64 + ni*16, GLB);
                wmma::load_matrix_sync(bl, sBlo + (ks*16)*GLB + wn2*64 + ni*16, GLB);
                #pragma unroll
                for (int mi = 0; mi < 2; mi++) {
                    wmma::mma_sync(acc[mi][ni], ah[mi], bh, acc[mi][ni]);
                    wmma::mma_sync(acc[mi][ni], ah[mi], bl, acc[mi][ni]);
                    wmma::mma_sync(acc[mi][ni], al[mi], bh, acc[mi][ni]);
                }
            }
        }
        __syncthreads();
    }

    #pragma unroll
    for (int mi = 0; mi < 2; mi++)
        #pragma unroll
        for (int ni = 0; ni < 4; ni++) {
            float* dst = g_D + ((size_t)mblk*128 + wm*32 + mi*16)*NC
                             + nblk*128 + wn2*64 + ni*16;
            wmma::store_matrix_sync(dst, acc[mi][ni], NC, wmma::mem_row_major);
        }
}

// ---------------------------------------------------------------------------
// Kernel C: tanh + xhat-weighted j-reduction over D + full node tail.
// ---------------------------------------------------------------------------
__global__ __launch_bounds__(256, 1) void k_reduce(
    const float* __restrict__ h,    const float* __restrict__ x,
    const float* __restrict__ v,
    const float* __restrict__ W_p1, const float* __restrict__ b_p1,
    const float* __restrict__ W_p2, const float* __restrict__ b_p2,
    const float* __restrict__ W_n1, const float* __restrict__ b_n1,
    const float* __restrict__ W_n2, const float* __restrict__ b_n2,
    const float* __restrict__ W_v1, const float* __restrict__ b_v1,
    const float* __restrict__ W_v2, const float* __restrict__ W_vmix,
    float* __restrict__ out)
{
    extern __shared__ __align__(16) float rsm[];
    float* sStage = rsm;               // 32*256
    float* sXh    = sStage + 32*256;   // 1024
    float* sComb  = sXh + 1024;        // 768
    float* sHes   = sComb + 768;       // 256
    float* sHi    = sHes + 256;        // 64
    float* sT1    = sHi + 64;          // 64
    float* sT2    = sT1 + 64;          // 64
    float* sHn    = sT2 + 64;          // 64
    float* sMisc  = sHn + 64;          // 16
    float* sCn    = sStage;            // alias after staging done

    const int t  = threadIdx.x;
    const int bi = blockIdx.x;
    const int b  = bi >> 8;
    const int i  = bi & 255;
    const int w  = t >> 5, lane = t & 31;

    sHes[t] = g_hes[bi*NC + t];
    if (t < 64) sHi[t] = h[(b*NN + i)*64 + t];
    {
        const int j = t;
        const float xi0 = x[(b*NN+i)*3+0], xi1 = x[(b*NN+i)*3+1], xi2 = x[(b*NN+i)*3+2];
        const float dx = x[(b*NN+j)*3+0]-xi0;
        const float dy = x[(b*NN+j)*3+1]-xi1;
        const float dz = x[(b*NN+j)*3+2]-xi2;
        const float ssq = dx*dx + dy*dy + dz*dz;
        const float dd  = sqrtf(fmaxf(ssq, 0.f) + 1e-5f);
        const float inv = 1.f/(dd + 1e-5f);
        sXh[j*4+0] = dx*inv; sXh[j*4+1] = dy*inv; sXh[j*4+2] = dz*inv;
    }
    __syncthreads();

    float a0 = 0.f, a1 = 0.f, a2 = 0.f;
    for (int tile = 0; tile < 8; tile++) {
        {
            const float4* gd = (const float4*)(g_D + ((size_t)bi*NN + tile*32)*NC);
            #pragma unroll
            for (int it = 0; it < 8; it++) {
                const int l = t + it*256;
                const int row = l >> 6, c4 = l & 63;
                *(float4*)(sStage + row*256 + c4*4) = gd[row*64 + c4];
            }
        }
        __syncthreads();
        #pragma unroll 8
        for (int r = 0; r < 32; r++) {
            const int j = tile*32 + r;
            const float tvv = tanhap(sStage[r*256 + t]);
            a0 += tvv * sXh[j*4+0];
            a1 += tvv * sXh[j*4+1];
            a2 += tvv * sXh[j*4+2];
        }
        __syncthreads();
    }
    sComb[t*3+0] = a0*(1.f/NN);
    sComb[t*3+1] = a1*(1.f/NN);
    sComb[t*3+2] = a2*(1.f/NN);
    __syncthreads();

    {
        const float c0 = sComb[t*3+0], c1 = sComb[t*3+1], c2 = sComb[t*3+2];
        sCn[t] = c0*c0 + c1*c1 + c2*c2;
    }
    __syncthreads();
    if (t < 64) {
        float a = b_p1[t];
        for (int c = 0; c < 256; c++) a += sCn[c]*W_p1[c*64 + t];
        sT1[t] = siluf(a);
    }
    __syncthreads();
    if (t < 64) {
        float a = b_p2[t];
        for (int c = 0; c < 64; c++) a += sT1[c]*W_p2[c*64 + t];
        sT2[t] = siluf(a);
    }
    __syncthreads();
    if (t < 64) {
        float a = b_n1[t];
        for (int r = 0; r < 64;  r++) a += sHi[r] *W_n1[r*64 + t];
        for (int r = 0; r < 256; r++) a += sHes[r]*W_n1[(64+r)*64 + t];
        for (int r = 0; r < 64;  r++) a += sT2[r] *W_n1[(320+r)*64 + t];
        sT1[t] = siluf(a);
    }
    __syncthreads();
    if (t < 64) {
        float a = b_n2[t];
        for (int c = 0; c < 64; c++) a += sT1[c]*W_n2[c*64 + t];
        const float hn = sHi[t] + siluf(a);
        sHn[t] = hn;
        out[(b*NN + i)*64 + t] = hn;
    }
    __syncthreads();
    if (t < 64) {
        float a = b_v1[t];
        for (int c = 0; c < 64; c++) a += sHn[c]*W_v1[c*64 + t];
        sT1[t] = siluf(a);
    }
    __syncthreads();
    if (w == 0) {
        float s = sT1[lane]*W_v2[lane] + sT1[lane+32]*W_v2[lane+32];
        #pragma unroll
        for (int o = 16; o; o >>= 1) s += __shfl_xor_sync(~0u, s, o);
        if (lane == 0) sMisc[0] = 2.f/(1.f + __expf(-s));
    }
    if (w >= 1 && w <= 3) {
        const int dd = w - 1;
        float s = 0.f;
        for (int q2 = 0; q2 < 8; q2++)
            s += sComb[(lane + 32*q2)*3 + dd]*W_vmix[lane + 32*q2];
        #pragma unroll
        for (int o = 16; o; o >>= 1) s += __shfl_xor_sync(~0u, s, o);
        if (lane == 0) sMisc[1+dd] = s;
    }
    __syncthreads();
    if (t < 3) {
        const float vn = sMisc[1+t] + sMisc[0]*v[(b*NN+i)*3 + t];
        const float xn = x[(b*NN+i)*3 + t] + vn;
        out[NB*NN*64 + (b*NN+i)*3 + t]           = xn;
        out[NB*NN*64 + NB*NN*3 + (b*NN+i)*3 + t] = vn;
    }
}

// ---------------------------------------------------------------------------
extern "C" void kernel_launch(void* const* d_in, const int* in_sizes, int n_in,
                              void* d_out, int out_size)
{
    const float* h      = (const float*)d_in[0];
    const float* x      = (const float*)d_in[1];
    const float* v      = (const float*)d_in[2];
    const float* W_in   = (const float*)d_in[3];
    const float* b_in   = (const float*)d_in[4];
    const float* means  = (const float*)d_in[5];
    const float* betas  = (const float*)d_in[6];
    const float* W_o1   = (const float*)d_in[7];
    const float* b_o1   = (const float*)d_in[8];
    const float* W_o2   = (const float*)d_in[9];
    const float* b_o2   = (const float*)d_in[10];
    const float* W_sem  = (const float*)d_in[11];
    const float* b_sem  = (const float*)d_in[12];
    const float* W_xmix = (const float*)d_in[13];
    const float* W_p1   = (const float*)d_in[14];
    const float* b_p1   = (const float*)d_in[15];
    const float* W_p2   = (const float*)d_in[16];
    const float* b_p2   = (const float*)d_in[17];
    const float* W_n1   = (const float*)d_in[18];
    const float* b_n1   = (const float*)d_in[19];
    const float* W_n2   = (const float*)d_in[20];
    const float* b_n2   = (const float*)d_in[21];
    const float* W_v1   = (const float*)d_in[22];
    const float* b_v1   = (const float*)d_in[23];
    const float* W_v2   = (const float*)d_in[24];
    const float* W_vmix = (const float*)d_in[25];
    float* out = (float*)d_out;

    const size_t smE = (size_t)(51*64 + 4096 + 256 + 3*NKF + 2*64 + 8 + 2*64
                                + NN*3 + 4*NN + 16 + 2*NN*65 + NN*4 + 64) * sizeof(float);
    const size_t smG = (size_t)(2*128*GLA + 2*64*GLB) * sizeof(__nv_bfloat16);
    const size_t smR = (size_t)(32*256 + 1024 + 768 + 256 + 4*64 + 16) * sizeof(float);

    cudaFuncSetAttribute(k_edge,   cudaFuncAttributeMaxDynamicSharedMemorySize, (int)smE);
    cudaFuncSetAttribute(k_gemm,   cudaFuncAttributeMaxDynamicSharedMemorySize, (int)smG);
    cudaFuncSetAttribute(k_reduce, cudaFuncAttributeMaxDynamicSharedMemorySize, (int)smR);

    k_prep<<<NC, NC>>>(W_xmix);
    k_pre2<<<NB*NN, 128>>>(h, W_in, W_o1);
    k_edge<<<NB*NN, 512, smE>>>(x, b_in, means, betas,
                                W_o1, b_o1, W_o2, b_o2, W_sem, b_sem);
    k_gemm<<<2048, 256, smG>>>();
    k_reduce<<<NB*NN, 256, smR>>>(h, x, v, W_p1, b_p1, W_p2, b_p2,
                                  W_n1, b_n1, W_n2, b_n2, W_v1, b_v1,
                                  W_v2, W_vmix, out);
}